// round 5
// baseline (speedup 1.0000x reference)
#include <cuda_runtime.h>
#include <math.h>

// Problem constants
#define NTHREADS 128
#define BATCH    128
#define TLEN     129
#define NSTEP    128   // TLEN-1
#define NWIN     16    // (TLEN-1)/8
#define OUTN     32

// ---- shared memory layout (float offsets) ----
// Packed weight layouts for conflict-free LDS.128:
//   V0p[j4][r] (16x128 float4), V1p[j4][r] (32x128), V2p[j4][r] (32x192)
//   element [j4][r] = float4{ V[r][4*j4 .. 4*j4+3] }
#define OFF_V0P 0        // 8192
#define OFF_V1P 8192     // 16384
#define OFF_V2P 24576    // 24576
#define OFF_R   49152    // 2048  (R row-major 32x64)
#define OFF_RB  51200    // 32
#define OFF_C0  51232    // 128
#define OFF_C1  51360    // 128
#define OFF_C2  51488    // 192
#define OFF_Y   51680    // 64
#define OFF_Y2  51744    // 64
#define OFF_K1  51808    // 64
#define OFF_K2  51872    // 64
#define OFF_S0  51936    // 128
#define OFF_G0  52064    // 128
#define OFF_S1  52192    // 128
#define OFF_G1  52320    // 128
#define OFF_M   52448    // 192  (tanh output, rows of m are the 3 JVP tangents)
#define OFF_TZ  52640    // 192  (1 - m^2)
#define OFF_TN0 52832    // 3*128
#define OFF_TN1 53216    // 3*128
#define OFF_J   53600    // 3*192
#define OFF_SLP 54176    // 16*8 (6 used per window)
#define OFF_DTS 54304    // 128
#define SMEM_FLOATS 54432
#define SMEM_BYTES  (SMEM_FLOATS * 4)

__device__ __forceinline__ float softplusf(float x) {
    // jax.nn.softplus == logaddexp(x, 0) == max(x,0) + log1p(exp(-|x|))
    return fmaxf(x, 0.0f) + log1pf(expf(-fabsf(x)));
}
__device__ __forceinline__ float sigmoidf_(float x) {
    return 1.0f / (1.0f + expf(-x));
}

// F(y) . s  for the RK2 step. All activations via smem; weights pre-packed in smem.
// Writes k (64 floats) to kout. Caller must __syncthreads() after return before
// reading kout, and guarantee yin is visible on entry.
__device__ __forceinline__ void eval_F(float* sm, int t,
                                       const float* __restrict__ yin,
                                       float* __restrict__ kout,
                                       const float* __restrict__ svec)
{
    const float4* __restrict__ V0p = (const float4*)(sm + OFF_V0P);
    const float4* __restrict__ V1p = (const float4*)(sm + OFF_V1P);
    const float4* __restrict__ V2p = (const float4*)(sm + OFF_V2P);
    float* s0  = sm + OFF_S0;  float* g0 = sm + OFF_G0;
    float* s1  = sm + OFF_S1;  float* g1 = sm + OFF_G1;
    float* msm = sm + OFF_M;   float* tz = sm + OFF_TZ;
    float* tn0 = sm + OFF_TN0; float* tn1 = sm + OFF_TN1;
    float* J   = sm + OFF_J;

    // ---------- forward layer 0: u0 = V0 @ y + c0 ----------
    {
        const float4* y4 = (const float4*)yin;
        float a0 = 0.f, a1 = 0.f, a2 = 0.f, a3 = 0.f;
#pragma unroll
        for (int j4 = 0; j4 < 16; j4++) {
            float4 w = V0p[j4 * NTHREADS + t];
            float4 a = y4[j4];
            a0 = fmaf(w.x, a.x, a0); a1 = fmaf(w.y, a.y, a1);
            a2 = fmaf(w.z, a.z, a2); a3 = fmaf(w.w, a.w, a3);
        }
        float u = sm[OFF_C0 + t] + ((a0 + a1) + (a2 + a3));
        s0[t] = softplusf(u);
        g0[t] = sigmoidf_(u);
    }
    __syncthreads();
    // ---------- forward layer 1 ----------
    {
        const float4* a4 = (const float4*)s0;
        float a0 = 0.f, a1 = 0.f, a2 = 0.f, a3 = 0.f;
#pragma unroll
        for (int j4 = 0; j4 < 32; j4++) {
            float4 w = V1p[j4 * NTHREADS + t];
            float4 a = a4[j4];
            a0 = fmaf(w.x, a.x, a0); a1 = fmaf(w.y, a.y, a1);
            a2 = fmaf(w.z, a.z, a2); a3 = fmaf(w.w, a.w, a3);
        }
        float u = sm[OFF_C1 + t] + ((a0 + a1) + (a2 + a3));
        s1[t] = softplusf(u);
        g1[t] = sigmoidf_(u);
    }
    __syncthreads();
    // ---------- forward layer 2 (192 rows: row t, and row 128+t for t<64) ----------
    {
        const float4* a4 = (const float4*)s1;
        float a0 = 0.f, a1 = 0.f, a2 = 0.f, a3 = 0.f;
#pragma unroll
        for (int j4 = 0; j4 < 32; j4++) {
            float4 w = V2p[j4 * 192 + t];
            float4 a = a4[j4];
            a0 = fmaf(w.x, a.x, a0); a1 = fmaf(w.y, a.y, a1);
            a2 = fmaf(w.z, a.z, a2); a3 = fmaf(w.w, a.w, a3);
        }
        float z  = sm[OFF_C2 + t] + ((a0 + a1) + (a2 + a3));
        float mm = tanhf(z);
        msm[t] = mm; tz[t] = 1.0f - mm * mm;
        if (t < 64) {
            float b0a = 0.f, b1a = 0.f, b2a = 0.f, b3a = 0.f;
#pragma unroll
            for (int j4 = 0; j4 < 32; j4++) {
                float4 w = V2p[j4 * 192 + 128 + t];
                float4 a = a4[j4];
                b0a = fmaf(w.x, a.x, b0a); b1a = fmaf(w.y, a.y, b1a);
                b2a = fmaf(w.z, a.z, b2a); b3a = fmaf(w.w, a.w, b3a);
            }
            float z2 = sm[OFF_C2 + 128 + t] + ((b0a + b1a) + (b2a + b3a));
            float m2 = tanhf(z2);
            msm[128 + t] = m2; tz[128 + t] = 1.0f - m2 * m2;
        }
    }
    __syncthreads();
    // ---------- JVP layer 0 (3 tangents = rows of m, batched => 3x weight reuse) ----------
    {
        const float4* m0 = (const float4*)(msm);
        const float4* m1 = (const float4*)(msm + 64);
        const float4* m2 = (const float4*)(msm + 128);
        float d0a = 0.f, d0b = 0.f, d1a = 0.f, d1b = 0.f, d2a = 0.f, d2b = 0.f;
#pragma unroll
        for (int j4 = 0; j4 < 16; j4++) {
            float4 w = V0p[j4 * NTHREADS + t];
            float4 a = m0[j4];
            d0a = fmaf(w.x, a.x, fmaf(w.y, a.y, d0a));
            d0b = fmaf(w.z, a.z, fmaf(w.w, a.w, d0b));
            float4 bb = m1[j4];
            d1a = fmaf(w.x, bb.x, fmaf(w.y, bb.y, d1a));
            d1b = fmaf(w.z, bb.z, fmaf(w.w, bb.w, d1b));
            float4 cc = m2[j4];
            d2a = fmaf(w.x, cc.x, fmaf(w.y, cc.y, d2a));
            d2b = fmaf(w.z, cc.z, fmaf(w.w, cc.w, d2b));
        }
        float g = g0[t];
        tn0[t]                = g * (d0a + d0b);
        tn0[NTHREADS + t]     = g * (d1a + d1b);
        tn0[2 * NTHREADS + t] = g * (d2a + d2b);
    }
    __syncthreads();
    // ---------- JVP layer 1 ----------
    {
        const float4* a0p = (const float4*)(tn0);
        const float4* a1p = (const float4*)(tn0 + NTHREADS);
        const float4* a2p = (const float4*)(tn0 + 2 * NTHREADS);
        float d0a = 0.f, d0b = 0.f, d1a = 0.f, d1b = 0.f, d2a = 0.f, d2b = 0.f;
#pragma unroll
        for (int j4 = 0; j4 < 32; j4++) {
            float4 w = V1p[j4 * NTHREADS + t];
            float4 a = a0p[j4];
            d0a = fmaf(w.x, a.x, fmaf(w.y, a.y, d0a));
            d0b = fmaf(w.z, a.z, fmaf(w.w, a.w, d0b));
            float4 bb = a1p[j4];
            d1a = fmaf(w.x, bb.x, fmaf(w.y, bb.y, d1a));
            d1b = fmaf(w.z, bb.z, fmaf(w.w, bb.w, d1b));
            float4 cc = a2p[j4];
            d2a = fmaf(w.x, cc.x, fmaf(w.y, cc.y, d2a));
            d2b = fmaf(w.z, cc.z, fmaf(w.w, cc.w, d2b));
        }
        float g = g1[t];
        tn1[t]                = g * (d0a + d0b);
        tn1[NTHREADS + t]     = g * (d1a + d1b);
        tn1[2 * NTHREADS + t] = g * (d2a + d2b);
    }
    __syncthreads();
    // ---------- JVP layer 2 ----------
    {
        const float4* a0p = (const float4*)(tn1);
        const float4* a1p = (const float4*)(tn1 + NTHREADS);
        const float4* a2p = (const float4*)(tn1 + 2 * NTHREADS);
        {
            float d0a = 0.f, d0b = 0.f, d1a = 0.f, d1b = 0.f, d2a = 0.f, d2b = 0.f;
#pragma unroll
            for (int j4 = 0; j4 < 32; j4++) {
                float4 w = V2p[j4 * 192 + t];
                float4 a = a0p[j4];
                d0a = fmaf(w.x, a.x, fmaf(w.y, a.y, d0a));
                d0b = fmaf(w.z, a.z, fmaf(w.w, a.w, d0b));
                float4 bb = a1p[j4];
                d1a = fmaf(w.x, bb.x, fmaf(w.y, bb.y, d1a));
                d1b = fmaf(w.z, bb.z, fmaf(w.w, bb.w, d1b));
                float4 cc = a2p[j4];
                d2a = fmaf(w.x, cc.x, fmaf(w.y, cc.y, d2a));
                d2b = fmaf(w.z, cc.z, fmaf(w.w, cc.w, d2b));
            }
            float tzv = tz[t];
            J[t]       = tzv * (d0a + d0b);
            J[192 + t] = tzv * (d1a + d1b);
            J[384 + t] = tzv * (d2a + d2b);
        }
        if (t < 64) {
            int r = 128 + t;
            float d0a = 0.f, d0b = 0.f, d1a = 0.f, d1b = 0.f, d2a = 0.f, d2b = 0.f;
#pragma unroll
            for (int j4 = 0; j4 < 32; j4++) {
                float4 w = V2p[j4 * 192 + r];
                float4 a = a0p[j4];
                d0a = fmaf(w.x, a.x, fmaf(w.y, a.y, d0a));
                d0b = fmaf(w.z, a.z, fmaf(w.w, a.w, d0b));
                float4 bb = a1p[j4];
                d1a = fmaf(w.x, bb.x, fmaf(w.y, bb.y, d1a));
                d1b = fmaf(w.z, bb.z, fmaf(w.w, bb.w, d1b));
                float4 cc = a2p[j4];
                d2a = fmaf(w.x, cc.x, fmaf(w.y, cc.y, d2a));
                d2b = fmaf(w.z, cc.z, fmaf(w.w, cc.w, d2b));
            }
            float tzv = tz[r];
            J[r]       = tzv * (d0a + d0b);
            J[192 + r] = tzv * (d1a + d1b);
            J[384 + r] = tzv * (d2a + d2b);
        }
    }
    __syncthreads();
    // ---------- combine: k[h] = m.T s[0:3] + br.T s[3:6] ----------
    if (t < 64) {
        // br0 = J[0,1]-J[1,0]; br1 = J[0,2]-J[2,0]; br2 = J[1,2]-J[2,1]
        float k =  msm[t]       * svec[0]
                 + msm[64 + t]  * svec[1]
                 + msm[128 + t] * svec[2]
                 + (J[64 + t]        - J[192 + t])      * svec[3]
                 + (J[128 + t]       - J[384 + t])      * svec[4]
                 + (J[192 + 128 + t] - J[384 + 64 + t]) * svec[5];
        kout[t] = k;
    }
}

// Output projection for current y: out_row[o] = tanh(dot(y, R[o,:]) + rb[o])
// 128 threads: 4 threads per output, 16-dim partials, shuffle-reduce.
__device__ __forceinline__ void write_out_row(const float* sm, int t, float* __restrict__ dst)
{
    int o = t >> 2, part = t & 3;
    const float* r = sm + OFF_R + o * 64 + part * 16;
    const float* y = sm + OFF_Y + part * 16;
    float s = 0.f;
#pragma unroll
    for (int j = 0; j < 16; j++) s = fmaf(r[j], y[j], s);
    s += __shfl_xor_sync(0xffffffffu, s, 1);
    s += __shfl_xor_sync(0xffffffffu, s, 2);
    if (part == 0) dst[o] = tanhf(s + sm[OFF_RB + o]);
}

__global__ void __launch_bounds__(NTHREADS, 1)
ncde_kernel(const float* __restrict__ ts, const float* __restrict__ x,
            const float* __restrict__ W0, const float* __restrict__ b0,
            const float* __restrict__ W1, const float* __restrict__ b1,
            const float* __restrict__ W2, const float* __restrict__ b2,
            const float* __restrict__ V0, const float* __restrict__ c0,
            const float* __restrict__ V1, const float* __restrict__ c1,
            const float* __restrict__ V2, const float* __restrict__ c2,
            const float* __restrict__ R,  const float* __restrict__ rb,
            float* __restrict__ out)
{
    extern __shared__ float sm[];
    const int t = threadIdx.x;
    const int b = blockIdx.x;

    // ---- stage weights into smem, packed for conflict-free LDS.128 ----
    for (int i = t; i < 16 * 128; i += NTHREADS) {
        int j4 = i >> 7, r = i & 127;
        ((float4*)(sm + OFF_V0P))[i] = *(const float4*)(V0 + r * 64 + j4 * 4);
    }
    for (int i = t; i < 32 * 128; i += NTHREADS) {
        int j4 = i >> 7, r = i & 127;
        ((float4*)(sm + OFF_V1P))[i] = *(const float4*)(V1 + r * 128 + j4 * 4);
    }
    for (int i = t; i < 32 * 192; i += NTHREADS) {
        int j4 = i / 192, r = i - j4 * 192;
        ((float4*)(sm + OFF_V2P))[i] = *(const float4*)(V2 + r * 128 + j4 * 4);
    }
    for (int i = t; i < 2048; i += NTHREADS) sm[OFF_R + i] = R[i];
    if (t < 32) sm[OFF_RB + t] = rb[t];
    sm[OFF_C0 + t] = c0[t];
    sm[OFF_C1 + t] = c1[t];
    for (int i = t; i < 192; i += NTHREADS) sm[OFF_C2 + i] = c2[i];

    // ---- per-batch: dt array ----
    {
        const float* tsb = ts + b * TLEN;
        for (int i = t; i < NSTEP; i += NTHREADS) sm[OFF_DTS + i] = tsb[i + 1] - tsb[i];
    }

    // ---- per-batch: window log-signature slopes (16 windows x 6 channels) ----
    if (t < NWIN) {
        const float* xp = x + (b * TLEN + t * 8) * 3;
        float p[9][3];
#pragma unroll
        for (int k = 0; k < 9; k++) {
            p[k][0] = xp[k * 3 + 0];
            p[k][1] = xp[k * 3 + 1];
            p[k][2] = xp[k * 3 + 2];
        }
        float a01 = 0.f, a10 = 0.f, a02 = 0.f, a20 = 0.f, a12 = 0.f, a21 = 0.f;
#pragma unroll
        for (int k = 0; k < 8; k++) {
            float r0 = p[k][0] - p[0][0], r1 = p[k][1] - p[0][1], r2 = p[k][2] - p[0][2];
            float d0 = p[k + 1][0] - p[k][0], d1 = p[k + 1][1] - p[k][1], d2 = p[k + 1][2] - p[k][2];
            a01 = fmaf(r0, d1, a01); a10 = fmaf(r1, d0, a10);
            a02 = fmaf(r0, d2, a02); a20 = fmaf(r2, d0, a20);
            a12 = fmaf(r1, d2, a12); a21 = fmaf(r2, d1, a21);
        }
        const float* tsb = ts + b * TLEN;
        float td = tsb[(t + 1) * 8] - tsb[t * 8];
        float* sl = sm + OFF_SLP + t * 8;
        sl[0] = (p[8][0] - p[0][0]) / td;
        sl[1] = (p[8][1] - p[0][1]) / td;
        sl[2] = (p[8][2] - p[0][2]) / td;
        sl[3] = (0.5f * (a01 - a10)) / td;
        sl[4] = (0.5f * (a02 - a20)) / td;
        sl[5] = (0.5f * (a12 - a21)) / td;
    }
    __syncthreads();

    // ---- init MLP: h0 = W2 @ sp(W1 @ sp(W0 @ x0 + b0) + b1) + b2 ----
    {
        const float* xp = x + b * TLEN * 3;
        float x0 = xp[0], x1 = xp[1], x2 = xp[2];
        float u = b0[t] + W0[t * 3] * x0 + W0[t * 3 + 1] * x1 + W0[t * 3 + 2] * x2;
        sm[OFF_S0 + t] = softplusf(u);
    }
    __syncthreads();
    {
        float acc = b1[t];
        const float* w = W1 + t * 128;
#pragma unroll 4
        for (int j = 0; j < 128; j++) acc = fmaf(w[j], sm[OFF_S0 + j], acc);
        sm[OFF_S1 + t] = softplusf(acc);
    }
    __syncthreads();
    if (t < 64) {
        float acc = b2[t];
        const float* w = W2 + t * 128;
#pragma unroll 4
        for (int j = 0; j < 128; j++) acc = fmaf(w[j], sm[OFF_S1 + j], acc);
        sm[OFF_Y + t] = acc;
    }
    __syncthreads();

    // ---- output row 0 (from h0) ----
    write_out_row(sm, t, out + (b * TLEN + 0) * OUTN);

    // ---- RK2 (Heun) scan over 128 steps ----
    for (int i = 0; i < NSTEP; i++) {
        float dt = sm[OFF_DTS + i];
        const float* svec = sm + OFF_SLP + ((i >> 3) << 3);

        eval_F(sm, t, sm + OFF_Y, sm + OFF_K1, svec);
        __syncthreads();
        if (t < 64) sm[OFF_Y2 + t] = sm[OFF_Y + t] + dt * sm[OFF_K1 + t];
        __syncthreads();
        eval_F(sm, t, sm + OFF_Y2, sm + OFF_K2, svec);
        __syncthreads();
        if (t < 64)
            sm[OFF_Y + t] = sm[OFF_Y + t] + 0.5f * dt * (sm[OFF_K1 + t] + sm[OFF_K2 + t]);
        __syncthreads();

        write_out_row(sm, t, out + (b * TLEN + i + 1) * OUTN);
    }
}

extern "C" void kernel_launch(void* const* d_in, const int* in_sizes, int n_in,
                              void* d_out, int out_size)
{
    const float* ts = (const float*)d_in[0];
    const float* x  = (const float*)d_in[1];
    const float* W0 = (const float*)d_in[2];
    const float* b0 = (const float*)d_in[3];
    const float* W1 = (const float*)d_in[4];
    const float* b1 = (const float*)d_in[5];
    const float* W2 = (const float*)d_in[6];
    const float* b2 = (const float*)d_in[7];
    const float* V0 = (const float*)d_in[8];
    const float* c0 = (const float*)d_in[9];
    const float* V1 = (const float*)d_in[10];
    const float* c1 = (const float*)d_in[11];
    const float* V2 = (const float*)d_in[12];
    const float* c2 = (const float*)d_in[13];
    const float* R  = (const float*)d_in[14];
    const float* rb = (const float*)d_in[15];
    float* out = (float*)d_out;

    cudaFuncSetAttribute(ncde_kernel, cudaFuncAttributeMaxDynamicSharedMemorySize, SMEM_BYTES);
    ncde_kernel<<<BATCH, NTHREADS, SMEM_BYTES>>>(ts, x, W0, b0, W1, b1, W2, b2,
                                                 V0, c0, V1, c1, V2, c2, R, rb, out);
}

// round 6
// speedup vs baseline: 1.0504x; 1.0504x over previous
#include <cuda_runtime.h>
#include <math.h>

// Problem constants
#define NTHREADS 128
#define BATCH    128
#define TLEN     129
#define NSTEP    128   // TLEN-1
#define NWIN     16    // (TLEN-1)/8
#define OUTN     32

// ---- shared memory layout (float offsets) ----
// Packed weight layouts for conflict-free LDS.128:
//   V0p[j4][r] (16x128 float4), V1p[j4][r] (32x128), V2p[j4][r] (32x192)
//   element [j4][r] = float4{ V[r][4*j4 .. 4*j4+3] }
#define OFF_V0P 0        // 8192
#define OFF_V1P 8192     // 16384
#define OFF_V2P 24576    // 24576
#define OFF_R   49152    // 2048  (R row-major 32x64)
#define OFF_RB  51200    // 32
#define OFF_C0  51232    // 128
#define OFF_C1  51360    // 128
#define OFF_C2  51488    // 192
#define OFF_Y   51680    // 64
#define OFF_Y2  51744    // 64
#define OFF_K1  51808    // 64
#define OFF_K2  51872    // 64
#define OFF_S0  51936    // 128
#define OFF_G0  52064    // 128
#define OFF_S1  52192    // 128
#define OFF_G1  52320    // 128
#define OFF_M   52448    // 192  (tanh output, rows of m are the 3 JVP tangents)
#define OFF_TZ  52640    // 192  (1 - m^2)
#define OFF_TN0 52832    // 3*128
#define OFF_TN1 53216    // 3*128
#define OFF_J   53600    // 3*192
#define OFF_SLP 54176    // 16*8 (6 used per window)
#define OFF_DTS 54304    // 128
#define SMEM_FLOATS 54432
#define SMEM_BYTES  (SMEM_FLOATS * 4)

__device__ __forceinline__ float softplusf(float x) {
    // jax.nn.softplus == logaddexp(x, 0) == max(x,0) + log1p(exp(-|x|))
    return fmaxf(x, 0.0f) + log1pf(expf(-fabsf(x)));
}
__device__ __forceinline__ float sigmoidf_(float x) {
    return 1.0f / (1.0f + expf(-x));
}

// F(y) . s  for the RK2 step. All activations via smem; weights pre-packed in smem.
// Writes k (64 floats) to kout. Caller must __syncthreads() after return before
// reading kout, and guarantee yin is visible on entry.
__device__ __forceinline__ void eval_F(float* sm, int t,
                                       const float* __restrict__ yin,
                                       float* __restrict__ kout,
                                       const float* __restrict__ svec)
{
    const float4* __restrict__ V0p = (const float4*)(sm + OFF_V0P);
    const float4* __restrict__ V1p = (const float4*)(sm + OFF_V1P);
    const float4* __restrict__ V2p = (const float4*)(sm + OFF_V2P);
    float* s0  = sm + OFF_S0;  float* g0 = sm + OFF_G0;
    float* s1  = sm + OFF_S1;  float* g1 = sm + OFF_G1;
    float* msm = sm + OFF_M;   float* tz = sm + OFF_TZ;
    float* tn0 = sm + OFF_TN0; float* tn1 = sm + OFF_TN1;
    float* J   = sm + OFF_J;

    // ---------- forward layer 0: u0 = V0 @ y + c0 ----------
    {
        const float4* y4 = (const float4*)yin;
        float a0 = 0.f, a1 = 0.f, a2 = 0.f, a3 = 0.f;
#pragma unroll
        for (int j4 = 0; j4 < 16; j4++) {
            float4 w = V0p[j4 * NTHREADS + t];
            float4 a = y4[j4];
            a0 = fmaf(w.x, a.x, a0); a1 = fmaf(w.y, a.y, a1);
            a2 = fmaf(w.z, a.z, a2); a3 = fmaf(w.w, a.w, a3);
        }
        float u = sm[OFF_C0 + t] + ((a0 + a1) + (a2 + a3));
        s0[t] = softplusf(u);
        g0[t] = sigmoidf_(u);
    }
    __syncthreads();
    // ---------- forward layer 1 ----------
    {
        const float4* a4 = (const float4*)s0;
        float a0 = 0.f, a1 = 0.f, a2 = 0.f, a3 = 0.f;
#pragma unroll
        for (int j4 = 0; j4 < 32; j4++) {
            float4 w = V1p[j4 * NTHREADS + t];
            float4 a = a4[j4];
            a0 = fmaf(w.x, a.x, a0); a1 = fmaf(w.y, a.y, a1);
            a2 = fmaf(w.z, a.z, a2); a3 = fmaf(w.w, a.w, a3);
        }
        float u = sm[OFF_C1 + t] + ((a0 + a1) + (a2 + a3));
        s1[t] = softplusf(u);
        g1[t] = sigmoidf_(u);
    }
    __syncthreads();
    // ---------- forward layer 2 (192 rows: row t, and row 128+t for t<64) ----------
    {
        const float4* a4 = (const float4*)s1;
        float a0 = 0.f, a1 = 0.f, a2 = 0.f, a3 = 0.f;
#pragma unroll
        for (int j4 = 0; j4 < 32; j4++) {
            float4 w = V2p[j4 * 192 + t];
            float4 a = a4[j4];
            a0 = fmaf(w.x, a.x, a0); a1 = fmaf(w.y, a.y, a1);
            a2 = fmaf(w.z, a.z, a2); a3 = fmaf(w.w, a.w, a3);
        }
        float z  = sm[OFF_C2 + t] + ((a0 + a1) + (a2 + a3));
        float mm = tanhf(z);
        msm[t] = mm; tz[t] = 1.0f - mm * mm;
        if (t < 64) {
            float b0a = 0.f, b1a = 0.f, b2a = 0.f, b3a = 0.f;
#pragma unroll
            for (int j4 = 0; j4 < 32; j4++) {
                float4 w = V2p[j4 * 192 + 128 + t];
                float4 a = a4[j4];
                b0a = fmaf(w.x, a.x, b0a); b1a = fmaf(w.y, a.y, b1a);
                b2a = fmaf(w.z, a.z, b2a); b3a = fmaf(w.w, a.w, b3a);
            }
            float z2 = sm[OFF_C2 + 128 + t] + ((b0a + b1a) + (b2a + b3a));
            float m2 = tanhf(z2);
            msm[128 + t] = m2; tz[128 + t] = 1.0f - m2 * m2;
        }
    }
    __syncthreads();
    // ---------- JVP layer 0 (3 tangents = rows of m, batched => 3x weight reuse) ----------
    {
        const float4* m0 = (const float4*)(msm);
        const float4* m1 = (const float4*)(msm + 64);
        const float4* m2 = (const float4*)(msm + 128);
        float d0a = 0.f, d0b = 0.f, d1a = 0.f, d1b = 0.f, d2a = 0.f, d2b = 0.f;
#pragma unroll
        for (int j4 = 0; j4 < 16; j4++) {
            float4 w = V0p[j4 * NTHREADS + t];
            float4 a = m0[j4];
            d0a = fmaf(w.x, a.x, fmaf(w.y, a.y, d0a));
            d0b = fmaf(w.z, a.z, fmaf(w.w, a.w, d0b));
            float4 bb = m1[j4];
            d1a = fmaf(w.x, bb.x, fmaf(w.y, bb.y, d1a));
            d1b = fmaf(w.z, bb.z, fmaf(w.w, bb.w, d1b));
            float4 cc = m2[j4];
            d2a = fmaf(w.x, cc.x, fmaf(w.y, cc.y, d2a));
            d2b = fmaf(w.z, cc.z, fmaf(w.w, cc.w, d2b));
        }
        float g = g0[t];
        tn0[t]                = g * (d0a + d0b);
        tn0[NTHREADS + t]     = g * (d1a + d1b);
        tn0[2 * NTHREADS + t] = g * (d2a + d2b);
    }
    __syncthreads();
    // ---------- JVP layer 1 ----------
    {
        const float4* a0p = (const float4*)(tn0);
        const float4* a1p = (const float4*)(tn0 + NTHREADS);
        const float4* a2p = (const float4*)(tn0 + 2 * NTHREADS);
        float d0a = 0.f, d0b = 0.f, d1a = 0.f, d1b = 0.f, d2a = 0.f, d2b = 0.f;
#pragma unroll
        for (int j4 = 0; j4 < 32; j4++) {
            float4 w = V1p[j4 * NTHREADS + t];
            float4 a = a0p[j4];
            d0a = fmaf(w.x, a.x, fmaf(w.y, a.y, d0a));
            d0b = fmaf(w.z, a.z, fmaf(w.w, a.w, d0b));
            float4 bb = a1p[j4];
            d1a = fmaf(w.x, bb.x, fmaf(w.y, bb.y, d1a));
            d1b = fmaf(w.z, bb.z, fmaf(w.w, bb.w, d1b));
            float4 cc = a2p[j4];
            d2a = fmaf(w.x, cc.x, fmaf(w.y, cc.y, d2a));
            d2b = fmaf(w.z, cc.z, fmaf(w.w, cc.w, d2b));
        }
        float g = g1[t];
        tn1[t]                = g * (d0a + d0b);
        tn1[NTHREADS + t]     = g * (d1a + d1b);
        tn1[2 * NTHREADS + t] = g * (d2a + d2b);
    }
    __syncthreads();
    // ---------- JVP layer 2 ----------
    {
        const float4* a0p = (const float4*)(tn1);
        const float4* a1p = (const float4*)(tn1 + NTHREADS);
        const float4* a2p = (const float4*)(tn1 + 2 * NTHREADS);
        {
            float d0a = 0.f, d0b = 0.f, d1a = 0.f, d1b = 0.f, d2a = 0.f, d2b = 0.f;
#pragma unroll
            for (int j4 = 0; j4 < 32; j4++) {
                float4 w = V2p[j4 * 192 + t];
                float4 a = a0p[j4];
                d0a = fmaf(w.x, a.x, fmaf(w.y, a.y, d0a));
                d0b = fmaf(w.z, a.z, fmaf(w.w, a.w, d0b));
                float4 bb = a1p[j4];
                d1a = fmaf(w.x, bb.x, fmaf(w.y, bb.y, d1a));
                d1b = fmaf(w.z, bb.z, fmaf(w.w, bb.w, d1b));
                float4 cc = a2p[j4];
                d2a = fmaf(w.x, cc.x, fmaf(w.y, cc.y, d2a));
                d2b = fmaf(w.z, cc.z, fmaf(w.w, cc.w, d2b));
            }
            float tzv = tz[t];
            J[t]       = tzv * (d0a + d0b);
            J[192 + t] = tzv * (d1a + d1b);
            J[384 + t] = tzv * (d2a + d2b);
        }
        if (t < 64) {
            int r = 128 + t;
            float d0a = 0.f, d0b = 0.f, d1a = 0.f, d1b = 0.f, d2a = 0.f, d2b = 0.f;
#pragma unroll
            for (int j4 = 0; j4 < 32; j4++) {
                float4 w = V2p[j4 * 192 + r];
                float4 a = a0p[j4];
                d0a = fmaf(w.x, a.x, fmaf(w.y, a.y, d0a));
                d0b = fmaf(w.z, a.z, fmaf(w.w, a.w, d0b));
                float4 bb = a1p[j4];
                d1a = fmaf(w.x, bb.x, fmaf(w.y, bb.y, d1a));
                d1b = fmaf(w.z, bb.z, fmaf(w.w, bb.w, d1b));
                float4 cc = a2p[j4];
                d2a = fmaf(w.x, cc.x, fmaf(w.y, cc.y, d2a));
                d2b = fmaf(w.z, cc.z, fmaf(w.w, cc.w, d2b));
            }
            float tzv = tz[r];
            J[r]       = tzv * (d0a + d0b);
            J[192 + r] = tzv * (d1a + d1b);
            J[384 + r] = tzv * (d2a + d2b);
        }
    }
    __syncthreads();
    // ---------- combine: k[h] = m.T s[0:3] + br.T s[3:6] ----------
    if (t < 64) {
        // br0 = J[0,1]-J[1,0]; br1 = J[0,2]-J[2,0]; br2 = J[1,2]-J[2,1]
        float k =  msm[t]       * svec[0]
                 + msm[64 + t]  * svec[1]
                 + msm[128 + t] * svec[2]
                 + (J[64 + t]        - J[192 + t])      * svec[3]
                 + (J[128 + t]       - J[384 + t])      * svec[4]
                 + (J[192 + 128 + t] - J[384 + 64 + t]) * svec[5];
        kout[t] = k;
    }
}

// Output projection for current y: out_row[o] = tanh(dot(y, R[o,:]) + rb[o])
// 128 threads: 4 threads per output, 16-dim partials, shuffle-reduce.
__device__ __forceinline__ void write_out_row(const float* sm, int t, float* __restrict__ dst)
{
    int o = t >> 2, part = t & 3;
    const float* r = sm + OFF_R + o * 64 + part * 16;
    const float* y = sm + OFF_Y + part * 16;
    float s = 0.f;
#pragma unroll
    for (int j = 0; j < 16; j++) s = fmaf(r[j], y[j], s);
    s += __shfl_xor_sync(0xffffffffu, s, 1);
    s += __shfl_xor_sync(0xffffffffu, s, 2);
    if (part == 0) dst[o] = tanhf(s + sm[OFF_RB + o]);
}

__global__ void __launch_bounds__(NTHREADS, 1)
ncde_kernel(const float* __restrict__ ts, const float* __restrict__ x,
            const float* __restrict__ W0, const float* __restrict__ b0,
            const float* __restrict__ W1, const float* __restrict__ b1,
            const float* __restrict__ W2, const float* __restrict__ b2,
            const float* __restrict__ V0, const float* __restrict__ c0,
            const float* __restrict__ V1, const float* __restrict__ c1,
            const float* __restrict__ V2, const float* __restrict__ c2,
            const float* __restrict__ R,  const float* __restrict__ rb,
            float* __restrict__ out)
{
    extern __shared__ float sm[];
    const int t = threadIdx.x;
    const int b = blockIdx.x;

    // ---- stage weights into smem, packed for conflict-free LDS.128 ----
    for (int i = t; i < 16 * 128; i += NTHREADS) {
        int j4 = i >> 7, r = i & 127;
        ((float4*)(sm + OFF_V0P))[i] = *(const float4*)(V0 + r * 64 + j4 * 4);
    }
    for (int i = t; i < 32 * 128; i += NTHREADS) {
        int j4 = i >> 7, r = i & 127;
        ((float4*)(sm + OFF_V1P))[i] = *(const float4*)(V1 + r * 128 + j4 * 4);
    }
    for (int i = t; i < 32 * 192; i += NTHREADS) {
        int j4 = i / 192, r = i - j4 * 192;
        ((float4*)(sm + OFF_V2P))[i] = *(const float4*)(V2 + r * 128 + j4 * 4);
    }
    for (int i = t; i < 2048; i += NTHREADS) sm[OFF_R + i] = R[i];
    if (t < 32) sm[OFF_RB + t] = rb[t];
    sm[OFF_C0 + t] = c0[t];
    sm[OFF_C1 + t] = c1[t];
    for (int i = t; i < 192; i += NTHREADS) sm[OFF_C2 + i] = c2[i];

    // ---- per-batch: dt array ----
    {
        const float* tsb = ts + b * TLEN;
        for (int i = t; i < NSTEP; i += NTHREADS) sm[OFF_DTS + i] = tsb[i + 1] - tsb[i];
    }

    // ---- per-batch: window log-signature slopes (16 windows x 6 channels) ----
    if (t < NWIN) {
        const float* xp = x + (b * TLEN + t * 8) * 3;
        float p[9][3];
#pragma unroll
        for (int k = 0; k < 9; k++) {
            p[k][0] = xp[k * 3 + 0];
            p[k][1] = xp[k * 3 + 1];
            p[k][2] = xp[k * 3 + 2];
        }
        float a01 = 0.f, a10 = 0.f, a02 = 0.f, a20 = 0.f, a12 = 0.f, a21 = 0.f;
#pragma unroll
        for (int k = 0; k < 8; k++) {
            float r0 = p[k][0] - p[0][0], r1 = p[k][1] - p[0][1], r2 = p[k][2] - p[0][2];
            float d0 = p[k + 1][0] - p[k][0], d1 = p[k + 1][1] - p[k][1], d2 = p[k + 1][2] - p[k][2];
            a01 = fmaf(r0, d1, a01); a10 = fmaf(r1, d0, a10);
            a02 = fmaf(r0, d2, a02); a20 = fmaf(r2, d0, a20);
            a12 = fmaf(r1, d2, a12); a21 = fmaf(r2, d1, a21);
        }
        const float* tsb = ts + b * TLEN;
        float td = tsb[(t + 1) * 8] - tsb[t * 8];
        float* sl = sm + OFF_SLP + t * 8;
        sl[0] = (p[8][0] - p[0][0]) / td;
        sl[1] = (p[8][1] - p[0][1]) / td;
        sl[2] = (p[8][2] - p[0][2]) / td;
        sl[3] = (0.5f * (a01 - a10)) / td;
        sl[4] = (0.5f * (a02 - a20)) / td;
        sl[5] = (0.5f * (a12 - a21)) / td;
    }
    __syncthreads();

    // ---- init MLP: h0 = W2 @ sp(W1 @ sp(W0 @ x0 + b0) + b1) + b2 ----
    {
        const float* xp = x + b * TLEN * 3;
        float x0 = xp[0], x1 = xp[1], x2 = xp[2];
        float u = b0[t] + W0[t * 3] * x0 + W0[t * 3 + 1] * x1 + W0[t * 3 + 2] * x2;
        sm[OFF_S0 + t] = softplusf(u);
    }
    __syncthreads();
    {
        float acc = b1[t];
        const float* w = W1 + t * 128;
#pragma unroll 4
        for (int j = 0; j < 128; j++) acc = fmaf(w[j], sm[OFF_S0 + j], acc);
        sm[OFF_S1 + t] = softplusf(acc);
    }
    __syncthreads();
    if (t < 64) {
        float acc = b2[t];
        const float* w = W2 + t * 128;
#pragma unroll 4
        for (int j = 0; j < 128; j++) acc = fmaf(w[j], sm[OFF_S1 + j], acc);
        sm[OFF_Y + t] = acc;
    }
    __syncthreads();

    // ---- output row 0 (from h0) ----
    write_out_row(sm, t, out + (b * TLEN + 0) * OUTN);

    // ---- RK2 (Heun) scan over 128 steps ----
    for (int i = 0; i < NSTEP; i++) {
        float dt = sm[OFF_DTS + i];
        const float* svec = sm + OFF_SLP + ((i >> 3) << 3);

        eval_F(sm, t, sm + OFF_Y, sm + OFF_K1, svec);
        __syncthreads();
        if (t < 64) sm[OFF_Y2 + t] = sm[OFF_Y + t] + dt * sm[OFF_K1 + t];
        __syncthreads();
        eval_F(sm, t, sm + OFF_Y2, sm + OFF_K2, svec);
        __syncthreads();
        if (t < 64)
            sm[OFF_Y + t] = sm[OFF_Y + t] + 0.5f * dt * (sm[OFF_K1 + t] + sm[OFF_K2 + t]);
        __syncthreads();

        write_out_row(sm, t, out + (b * TLEN + i + 1) * OUTN);
    }
}

extern "C" void kernel_launch(void* const* d_in, const int* in_sizes, int n_in,
                              void* d_out, int out_size)
{
    const float* ts = (const float*)d_in[0];
    const float* x  = (const float*)d_in[1];
    const float* W0 = (const float*)d_in[2];
    const float* b0 = (const float*)d_in[3];
    const float* W1 = (const float*)d_in[4];
    const float* b1 = (const float*)d_in[5];
    const float* W2 = (const float*)d_in[6];
    const float* b2 = (const float*)d_in[7];
    const float* V0 = (const float*)d_in[8];
    const float* c0 = (const float*)d_in[9];
    const float* V1 = (const float*)d_in[10];
    const float* c1 = (const float*)d_in[11];
    const float* V2 = (const float*)d_in[12];
    const float* c2 = (const float*)d_in[13];
    const float* R  = (const float*)d_in[14];
    const float* rb = (const float*)d_in[15];
    float* out = (float*)d_out;

    cudaFuncSetAttribute(ncde_kernel, cudaFuncAttributeMaxDynamicSharedMemorySize, SMEM_BYTES);
    ncde_kernel<<<BATCH, NTHREADS, SMEM_BYTES>>>(ts, x, W0, b0, W1, b1, W2, b2,
                                                 V0, c0, V1, c1, V2, c2, R, rb, out);
}

// round 7
// speedup vs baseline: 1.0504x; 1.0000x over previous
#include <cuda_runtime.h>
#include <math.h>

// Problem constants
#define NTHREADS 128
#define BATCH    128
#define TLEN     129
#define NSTEP    128   // TLEN-1
#define NWIN     16    // (TLEN-1)/8
#define OUTN     32

// ---- shared memory layout (float offsets) ----
// Packed weight layouts for conflict-free LDS.128:
//   V0p[j4][r] (16x128 float4), V1p[j4][r] (32x128), V2p[j4][r] (32x192)
//   element [j4][r] = float4{ V[r][4*j4 .. 4*j4+3] }
#define OFF_V0P 0        // 8192
#define OFF_V1P 8192     // 16384
#define OFF_V2P 24576    // 24576
#define OFF_R   49152    // 2048  (R row-major 32x64)
#define OFF_RB  51200    // 32
#define OFF_C0  51232    // 128
#define OFF_C1  51360    // 128
#define OFF_C2  51488    // 192
#define OFF_Y   51680    // 64
#define OFF_Y2  51744    // 64
#define OFF_K1  51808    // 64
#define OFF_K2  51872    // 64
#define OFF_S0  51936    // 128
#define OFF_G0  52064    // 128
#define OFF_S1  52192    // 128
#define OFF_G1  52320    // 128
#define OFF_M   52448    // 192  (tanh output, rows of m are the 3 JVP tangents)
#define OFF_TZ  52640    // 192  (1 - m^2)
#define OFF_TN0 52832    // 3*128
#define OFF_TN1 53216    // 3*128
#define OFF_J   53600    // 3*192
#define OFF_SLP 54176    // 16*8 (6 used per window)
#define OFF_DTS 54304    // 128
#define SMEM_FLOATS 54432
#define SMEM_BYTES  (SMEM_FLOATS * 4)

__device__ __forceinline__ float softplusf(float x) {
    // jax.nn.softplus == logaddexp(x, 0) == max(x,0) + log1p(exp(-|x|))
    return fmaxf(x, 0.0f) + log1pf(expf(-fabsf(x)));
}
__device__ __forceinline__ float sigmoidf_(float x) {
    return 1.0f / (1.0f + expf(-x));
}

// F(y) . s  for the RK2 step. All activations via smem; weights pre-packed in smem.
// Writes k (64 floats) to kout. Caller must __syncthreads() after return before
// reading kout, and guarantee yin is visible on entry.
__device__ __forceinline__ void eval_F(float* sm, int t,
                                       const float* __restrict__ yin,
                                       float* __restrict__ kout,
                                       const float* __restrict__ svec)
{
    const float4* __restrict__ V0p = (const float4*)(sm + OFF_V0P);
    const float4* __restrict__ V1p = (const float4*)(sm + OFF_V1P);
    const float4* __restrict__ V2p = (const float4*)(sm + OFF_V2P);
    float* s0  = sm + OFF_S0;  float* g0 = sm + OFF_G0;
    float* s1  = sm + OFF_S1;  float* g1 = sm + OFF_G1;
    float* msm = sm + OFF_M;   float* tz = sm + OFF_TZ;
    float* tn0 = sm + OFF_TN0; float* tn1 = sm + OFF_TN1;
    float* J   = sm + OFF_J;

    // ---------- forward layer 0: u0 = V0 @ y + c0 ----------
    {
        const float4* y4 = (const float4*)yin;
        float a0 = 0.f, a1 = 0.f, a2 = 0.f, a3 = 0.f;
#pragma unroll
        for (int j4 = 0; j4 < 16; j4++) {
            float4 w = V0p[j4 * NTHREADS + t];
            float4 a = y4[j4];
            a0 = fmaf(w.x, a.x, a0); a1 = fmaf(w.y, a.y, a1);
            a2 = fmaf(w.z, a.z, a2); a3 = fmaf(w.w, a.w, a3);
        }
        float u = sm[OFF_C0 + t] + ((a0 + a1) + (a2 + a3));
        s0[t] = softplusf(u);
        g0[t] = sigmoidf_(u);
    }
    __syncthreads();
    // ---------- forward layer 1 ----------
    {
        const float4* a4 = (const float4*)s0;
        float a0 = 0.f, a1 = 0.f, a2 = 0.f, a3 = 0.f;
#pragma unroll
        for (int j4 = 0; j4 < 32; j4++) {
            float4 w = V1p[j4 * NTHREADS + t];
            float4 a = a4[j4];
            a0 = fmaf(w.x, a.x, a0); a1 = fmaf(w.y, a.y, a1);
            a2 = fmaf(w.z, a.z, a2); a3 = fmaf(w.w, a.w, a3);
        }
        float u = sm[OFF_C1 + t] + ((a0 + a1) + (a2 + a3));
        s1[t] = softplusf(u);
        g1[t] = sigmoidf_(u);
    }
    __syncthreads();
    // ---------- forward layer 2 (192 rows: row t, and row 128+t for t<64) ----------
    {
        const float4* a4 = (const float4*)s1;
        float a0 = 0.f, a1 = 0.f, a2 = 0.f, a3 = 0.f;
#pragma unroll
        for (int j4 = 0; j4 < 32; j4++) {
            float4 w = V2p[j4 * 192 + t];
            float4 a = a4[j4];
            a0 = fmaf(w.x, a.x, a0); a1 = fmaf(w.y, a.y, a1);
            a2 = fmaf(w.z, a.z, a2); a3 = fmaf(w.w, a.w, a3);
        }
        float z  = sm[OFF_C2 + t] + ((a0 + a1) + (a2 + a3));
        float mm = tanhf(z);
        msm[t] = mm; tz[t] = 1.0f - mm * mm;
        if (t < 64) {
            float b0a = 0.f, b1a = 0.f, b2a = 0.f, b3a = 0.f;
#pragma unroll
            for (int j4 = 0; j4 < 32; j4++) {
                float4 w = V2p[j4 * 192 + 128 + t];
                float4 a = a4[j4];
                b0a = fmaf(w.x, a.x, b0a); b1a = fmaf(w.y, a.y, b1a);
                b2a = fmaf(w.z, a.z, b2a); b3a = fmaf(w.w, a.w, b3a);
            }
            float z2 = sm[OFF_C2 + 128 + t] + ((b0a + b1a) + (b2a + b3a));
            float m2 = tanhf(z2);
            msm[128 + t] = m2; tz[128 + t] = 1.0f - m2 * m2;
        }
    }
    __syncthreads();
    // ---------- JVP layer 0 (3 tangents = rows of m, batched => 3x weight reuse) ----------
    {
        const float4* m0 = (const float4*)(msm);
        const float4* m1 = (const float4*)(msm + 64);
        const float4* m2 = (const float4*)(msm + 128);
        float d0a = 0.f, d0b = 0.f, d1a = 0.f, d1b = 0.f, d2a = 0.f, d2b = 0.f;
#pragma unroll
        for (int j4 = 0; j4 < 16; j4++) {
            float4 w = V0p[j4 * NTHREADS + t];
            float4 a = m0[j4];
            d0a = fmaf(w.x, a.x, fmaf(w.y, a.y, d0a));
            d0b = fmaf(w.z, a.z, fmaf(w.w, a.w, d0b));
            float4 bb = m1[j4];
            d1a = fmaf(w.x, bb.x, fmaf(w.y, bb.y, d1a));
            d1b = fmaf(w.z, bb.z, fmaf(w.w, bb.w, d1b));
            float4 cc = m2[j4];
            d2a = fmaf(w.x, cc.x, fmaf(w.y, cc.y, d2a));
            d2b = fmaf(w.z, cc.z, fmaf(w.w, cc.w, d2b));
        }
        float g = g0[t];
        tn0[t]                = g * (d0a + d0b);
        tn0[NTHREADS + t]     = g * (d1a + d1b);
        tn0[2 * NTHREADS + t] = g * (d2a + d2b);
    }
    __syncthreads();
    // ---------- JVP layer 1 ----------
    {
        const float4* a0p = (const float4*)(tn0);
        const float4* a1p = (const float4*)(tn0 + NTHREADS);
        const float4* a2p = (const float4*)(tn0 + 2 * NTHREADS);
        float d0a = 0.f, d0b = 0.f, d1a = 0.f, d1b = 0.f, d2a = 0.f, d2b = 0.f;
#pragma unroll
        for (int j4 = 0; j4 < 32; j4++) {
            float4 w = V1p[j4 * NTHREADS + t];
            float4 a = a0p[j4];
            d0a = fmaf(w.x, a.x, fmaf(w.y, a.y, d0a));
            d0b = fmaf(w.z, a.z, fmaf(w.w, a.w, d0b));
            float4 bb = a1p[j4];
            d1a = fmaf(w.x, bb.x, fmaf(w.y, bb.y, d1a));
            d1b = fmaf(w.z, bb.z, fmaf(w.w, bb.w, d1b));
            float4 cc = a2p[j4];
            d2a = fmaf(w.x, cc.x, fmaf(w.y, cc.y, d2a));
            d2b = fmaf(w.z, cc.z, fmaf(w.w, cc.w, d2b));
        }
        float g = g1[t];
        tn1[t]                = g * (d0a + d0b);
        tn1[NTHREADS + t]     = g * (d1a + d1b);
        tn1[2 * NTHREADS + t] = g * (d2a + d2b);
    }
    __syncthreads();
    // ---------- JVP layer 2 ----------
    {
        const float4* a0p = (const float4*)(tn1);
        const float4* a1p = (const float4*)(tn1 + NTHREADS);
        const float4* a2p = (const float4*)(tn1 + 2 * NTHREADS);
        {
            float d0a = 0.f, d0b = 0.f, d1a = 0.f, d1b = 0.f, d2a = 0.f, d2b = 0.f;
#pragma unroll
            for (int j4 = 0; j4 < 32; j4++) {
                float4 w = V2p[j4 * 192 + t];
                float4 a = a0p[j4];
                d0a = fmaf(w.x, a.x, fmaf(w.y, a.y, d0a));
                d0b = fmaf(w.z, a.z, fmaf(w.w, a.w, d0b));
                float4 bb = a1p[j4];
                d1a = fmaf(w.x, bb.x, fmaf(w.y, bb.y, d1a));
                d1b = fmaf(w.z, bb.z, fmaf(w.w, bb.w, d1b));
                float4 cc = a2p[j4];
                d2a = fmaf(w.x, cc.x, fmaf(w.y, cc.y, d2a));
                d2b = fmaf(w.z, cc.z, fmaf(w.w, cc.w, d2b));
            }
            float tzv = tz[t];
            J[t]       = tzv * (d0a + d0b);
            J[192 + t] = tzv * (d1a + d1b);
            J[384 + t] = tzv * (d2a + d2b);
        }
        if (t < 64) {
            int r = 128 + t;
            float d0a = 0.f, d0b = 0.f, d1a = 0.f, d1b = 0.f, d2a = 0.f, d2b = 0.f;
#pragma unroll
            for (int j4 = 0; j4 < 32; j4++) {
                float4 w = V2p[j4 * 192 + r];
                float4 a = a0p[j4];
                d0a = fmaf(w.x, a.x, fmaf(w.y, a.y, d0a));
                d0b = fmaf(w.z, a.z, fmaf(w.w, a.w, d0b));
                float4 bb = a1p[j4];
                d1a = fmaf(w.x, bb.x, fmaf(w.y, bb.y, d1a));
                d1b = fmaf(w.z, bb.z, fmaf(w.w, bb.w, d1b));
                float4 cc = a2p[j4];
                d2a = fmaf(w.x, cc.x, fmaf(w.y, cc.y, d2a));
                d2b = fmaf(w.z, cc.z, fmaf(w.w, cc.w, d2b));
            }
            float tzv = tz[r];
            J[r]       = tzv * (d0a + d0b);
            J[192 + r] = tzv * (d1a + d1b);
            J[384 + r] = tzv * (d2a + d2b);
        }
    }
    __syncthreads();
    // ---------- combine: k[h] = m.T s[0:3] + br.T s[3:6] ----------
    if (t < 64) {
        // br0 = J[0,1]-J[1,0]; br1 = J[0,2]-J[2,0]; br2 = J[1,2]-J[2,1]
        float k =  msm[t]       * svec[0]
                 + msm[64 + t]  * svec[1]
                 + msm[128 + t] * svec[2]
                 + (J[64 + t]        - J[192 + t])      * svec[3]
                 + (J[128 + t]       - J[384 + t])      * svec[4]
                 + (J[192 + 128 + t] - J[384 + 64 + t]) * svec[5];
        kout[t] = k;
    }
}

// Output projection for current y: out_row[o] = tanh(dot(y, R[o,:]) + rb[o])
// 128 threads: 4 threads per output, 16-dim partials, shuffle-reduce.
__device__ __forceinline__ void write_out_row(const float* sm, int t, float* __restrict__ dst)
{
    int o = t >> 2, part = t & 3;
    const float* r = sm + OFF_R + o * 64 + part * 16;
    const float* y = sm + OFF_Y + part * 16;
    float s = 0.f;
#pragma unroll
    for (int j = 0; j < 16; j++) s = fmaf(r[j], y[j], s);
    s += __shfl_xor_sync(0xffffffffu, s, 1);
    s += __shfl_xor_sync(0xffffffffu, s, 2);
    if (part == 0) dst[o] = tanhf(s + sm[OFF_RB + o]);
}

__global__ void __launch_bounds__(NTHREADS, 1)
ncde_kernel(const float* __restrict__ ts, const float* __restrict__ x,
            const float* __restrict__ W0, const float* __restrict__ b0,
            const float* __restrict__ W1, const float* __restrict__ b1,
            const float* __restrict__ W2, const float* __restrict__ b2,
            const float* __restrict__ V0, const float* __restrict__ c0,
            const float* __restrict__ V1, const float* __restrict__ c1,
            const float* __restrict__ V2, const float* __restrict__ c2,
            const float* __restrict__ R,  const float* __restrict__ rb,
            float* __restrict__ out)
{
    extern __shared__ float sm[];
    const int t = threadIdx.x;
    const int b = blockIdx.x;

    // ---- stage weights into smem, packed for conflict-free LDS.128 ----
    for (int i = t; i < 16 * 128; i += NTHREADS) {
        int j4 = i >> 7, r = i & 127;
        ((float4*)(sm + OFF_V0P))[i] = *(const float4*)(V0 + r * 64 + j4 * 4);
    }
    for (int i = t; i < 32 * 128; i += NTHREADS) {
        int j4 = i >> 7, r = i & 127;
        ((float4*)(sm + OFF_V1P))[i] = *(const float4*)(V1 + r * 128 + j4 * 4);
    }
    for (int i = t; i < 32 * 192; i += NTHREADS) {
        int j4 = i / 192, r = i - j4 * 192;
        ((float4*)(sm + OFF_V2P))[i] = *(const float4*)(V2 + r * 128 + j4 * 4);
    }
    for (int i = t; i < 2048; i += NTHREADS) sm[OFF_R + i] = R[i];
    if (t < 32) sm[OFF_RB + t] = rb[t];
    sm[OFF_C0 + t] = c0[t];
    sm[OFF_C1 + t] = c1[t];
    for (int i = t; i < 192; i += NTHREADS) sm[OFF_C2 + i] = c2[i];

    // ---- per-batch: dt array ----
    {
        const float* tsb = ts + b * TLEN;
        for (int i = t; i < NSTEP; i += NTHREADS) sm[OFF_DTS + i] = tsb[i + 1] - tsb[i];
    }

    // ---- per-batch: window log-signature slopes (16 windows x 6 channels) ----
    if (t < NWIN) {
        const float* xp = x + (b * TLEN + t * 8) * 3;
        float p[9][3];
#pragma unroll
        for (int k = 0; k < 9; k++) {
            p[k][0] = xp[k * 3 + 0];
            p[k][1] = xp[k * 3 + 1];
            p[k][2] = xp[k * 3 + 2];
        }
        float a01 = 0.f, a10 = 0.f, a02 = 0.f, a20 = 0.f, a12 = 0.f, a21 = 0.f;
#pragma unroll
        for (int k = 0; k < 8; k++) {
            float r0 = p[k][0] - p[0][0], r1 = p[k][1] - p[0][1], r2 = p[k][2] - p[0][2];
            float d0 = p[k + 1][0] - p[k][0], d1 = p[k + 1][1] - p[k][1], d2 = p[k + 1][2] - p[k][2];
            a01 = fmaf(r0, d1, a01); a10 = fmaf(r1, d0, a10);
            a02 = fmaf(r0, d2, a02); a20 = fmaf(r2, d0, a20);
            a12 = fmaf(r1, d2, a12); a21 = fmaf(r2, d1, a21);
        }
        const float* tsb = ts + b * TLEN;
        float td = tsb[(t + 1) * 8] - tsb[t * 8];
        float* sl = sm + OFF_SLP + t * 8;
        sl[0] = (p[8][0] - p[0][0]) / td;
        sl[1] = (p[8][1] - p[0][1]) / td;
        sl[2] = (p[8][2] - p[0][2]) / td;
        sl[3] = (0.5f * (a01 - a10)) / td;
        sl[4] = (0.5f * (a02 - a20)) / td;
        sl[5] = (0.5f * (a12 - a21)) / td;
    }
    __syncthreads();

    // ---- init MLP: h0 = W2 @ sp(W1 @ sp(W0 @ x0 + b0) + b1) + b2 ----
    {
        const float* xp = x + b * TLEN * 3;
        float x0 = xp[0], x1 = xp[1], x2 = xp[2];
        float u = b0[t] + W0[t * 3] * x0 + W0[t * 3 + 1] * x1 + W0[t * 3 + 2] * x2;
        sm[OFF_S0 + t] = softplusf(u);
    }
    __syncthreads();
    {
        float acc = b1[t];
        const float* w = W1 + t * 128;
#pragma unroll 4
        for (int j = 0; j < 128; j++) acc = fmaf(w[j], sm[OFF_S0 + j], acc);
        sm[OFF_S1 + t] = softplusf(acc);
    }
    __syncthreads();
    if (t < 64) {
        float acc = b2[t];
        const float* w = W2 + t * 128;
#pragma unroll 4
        for (int j = 0; j < 128; j++) acc = fmaf(w[j], sm[OFF_S1 + j], acc);
        sm[OFF_Y + t] = acc;
    }
    __syncthreads();

    // ---- output row 0 (from h0) ----
    write_out_row(sm, t, out + (b * TLEN + 0) * OUTN);

    // ---- RK2 (Heun) scan over 128 steps ----
    for (int i = 0; i < NSTEP; i++) {
        float dt = sm[OFF_DTS + i];
        const float* svec = sm + OFF_SLP + ((i >> 3) << 3);

        eval_F(sm, t, sm + OFF_Y, sm + OFF_K1, svec);
        __syncthreads();
        if (t < 64) sm[OFF_Y2 + t] = sm[OFF_Y + t] + dt * sm[OFF_K1 + t];
        __syncthreads();
        eval_F(sm, t, sm + OFF_Y2, sm + OFF_K2, svec);
        __syncthreads();
        if (t < 64)
            sm[OFF_Y + t] = sm[OFF_Y + t] + 0.5f * dt * (sm[OFF_K1 + t] + sm[OFF_K2 + t]);
        __syncthreads();

        write_out_row(sm, t, out + (b * TLEN + i + 1) * OUTN);
    }
}

extern "C" void kernel_launch(void* const* d_in, const int* in_sizes, int n_in,
                              void* d_out, int out_size)
{
    const float* ts = (const float*)d_in[0];
    const float* x  = (const float*)d_in[1];
    const float* W0 = (const float*)d_in[2];
    const float* b0 = (const float*)d_in[3];
    const float* W1 = (const float*)d_in[4];
    const float* b1 = (const float*)d_in[5];
    const float* W2 = (const float*)d_in[6];
    const float* b2 = (const float*)d_in[7];
    const float* V0 = (const float*)d_in[8];
    const float* c0 = (const float*)d_in[9];
    const float* V1 = (const float*)d_in[10];
    const float* c1 = (const float*)d_in[11];
    const float* V2 = (const float*)d_in[12];
    const float* c2 = (const float*)d_in[13];
    const float* R  = (const float*)d_in[14];
    const float* rb = (const float*)d_in[15];
    float* out = (float*)d_out;

    cudaFuncSetAttribute(ncde_kernel, cudaFuncAttributeMaxDynamicSharedMemorySize, SMEM_BYTES);
    ncde_kernel<<<BATCH, NTHREADS, SMEM_BYTES>>>(ts, x, W0, b0, W1, b1, W2, b2,
                                                 V0, c0, V1, c1, V2, c2, R, rb, out);
}

// round 8
// speedup vs baseline: 1.7931x; 1.7071x over previous
#include <cuda_runtime.h>
#include <math.h>

// Problem constants
#define NTHREADS 256
#define BATCH    128
#define TLEN     129
#define NSTEP    128   // TLEN-1
#define NWIN     16    // (TLEN-1)/8
#define OUTN     32

// ---- shared memory layout (float offsets) ----
// Split-K packed weights for 256-thread row-pair scheme.
//   V0q[i][tid] (8x256 float4):  tid=2r+h -> V0[r][(2i+h)*4 ..]
//   V1q[i][tid] (16x256):        tid=2r+h -> V1[r][(2i+h)*4 ..]
//   V2qa[i][tid] (16x256):       tid=2r+h -> V2[r][(2i+h)*4 ..]        (rows 0..127)
//   V2qb[i][tid] (8x256):        tid=4r'+q -> V2[128+r'][(4i+q)*4 ..]  (rows 128..191)
#define OFF_V0Q  0        // 8192
#define OFF_V1Q  8192     // 16384
#define OFF_V2QA 24576    // 16384
#define OFF_V2QB 40960    // 8192
#define OFF_R    49152    // 2048  (R row-major 32x64)
#define OFF_RB   51200    // 32
#define OFF_C0   51232    // 128
#define OFF_C1   51360    // 128
#define OFF_C2   51488    // 192
#define OFF_Y    51680    // 64
#define OFF_Y2   51744    // 64
#define OFF_S0   51808    // 128
#define OFF_G0   51936    // 128
#define OFF_S1   52064    // 128
#define OFF_G1   52192    // 128
#define OFF_M    52320    // 192
#define OFF_TZ   52512    // 192
#define OFF_TN0  52704    // 3*128
#define OFF_TN1  53088    // 3*128
#define OFF_J    53472    // 3*192
#define OFF_SLP  54048    // 16*8 (6 used per window)
#define OFF_DTS  54176    // 128
#define SMEM_FLOATS 54304
#define SMEM_BYTES  (SMEM_FLOATS * 4)

__device__ __forceinline__ float softplusf(float x) {
    // jax.nn.softplus == max(x,0) + log1p(exp(-|x|))
    return fmaxf(x, 0.0f) + log1pf(expf(-fabsf(x)));
}
__device__ __forceinline__ float sigmoidf_(float x) {
    return 1.0f / (1.0f + expf(-x));
}

// F(y) . s. 256 threads, split-K pair/quad scheme. Returns k[t] in a register
// (valid for tid<64). Caller must ensure yin visible on entry (barrier) and
// must barrier before any consumer reads shared state written here again.
__device__ __forceinline__ float eval_F(float* sm, int tid,
                                        const float* __restrict__ yin,
                                        const float* __restrict__ svec)
{
    const int rh = tid >> 1, h = tid & 1;    // pair mapping (128 rows x 2)
    const int rq = tid >> 2, q = tid & 3;    // quad mapping (64 rows x 4)
    const float4* __restrict__ V0q  = (const float4*)(sm + OFF_V0Q);
    const float4* __restrict__ V1q  = (const float4*)(sm + OFF_V1Q);
    const float4* __restrict__ V2qa = (const float4*)(sm + OFF_V2QA);
    const float4* __restrict__ V2qb = (const float4*)(sm + OFF_V2QB);
    float* s0  = sm + OFF_S0;  float* g0 = sm + OFF_G0;
    float* s1  = sm + OFF_S1;  float* g1 = sm + OFF_G1;
    float* msm = sm + OFF_M;   float* tz = sm + OFF_TZ;
    float* tn0 = sm + OFF_TN0; float* tn1 = sm + OFF_TN1;
    float* J   = sm + OFF_J;

    // ---------- forward layer 0: u0 = V0 @ y + c0 ----------
    {
        const float4* y4 = (const float4*)yin;
        float a = 0.f, bacc = 0.f;
#pragma unroll
        for (int i = 0; i < 8; i++) {
            float4 w = V0q[i * 256 + tid];
            float4 v = y4[2 * i + h];
            a    = fmaf(w.x, v.x, a);    bacc = fmaf(w.y, v.y, bacc);
            a    = fmaf(w.z, v.z, a);    bacc = fmaf(w.w, v.w, bacc);
        }
        float s = a + bacc;
        s += __shfl_xor_sync(0xffffffffu, s, 1);
        if (h == 0) {
            float u = sm[OFF_C0 + rh] + s;
            s0[rh] = softplusf(u);
            g0[rh] = sigmoidf_(u);
        }
    }
    __syncthreads();
    // ---------- forward layer 1 ----------
    {
        const float4* a4 = (const float4*)s0;
        float a = 0.f, bacc = 0.f;
#pragma unroll
        for (int i = 0; i < 16; i++) {
            float4 w = V1q[i * 256 + tid];
            float4 v = a4[2 * i + h];
            a    = fmaf(w.x, v.x, a);    bacc = fmaf(w.y, v.y, bacc);
            a    = fmaf(w.z, v.z, a);    bacc = fmaf(w.w, v.w, bacc);
        }
        float s = a + bacc;
        s += __shfl_xor_sync(0xffffffffu, s, 1);
        if (h == 0) {
            float u = sm[OFF_C1 + rh] + s;
            s1[rh] = softplusf(u);
            g1[rh] = sigmoidf_(u);
        }
    }
    __syncthreads();
    // ---------- forward layer 2 (192 rows) ----------
    {
        const float4* a4 = (const float4*)s1;
        {   // rows 0..127 (pairs)
            float a = 0.f, bacc = 0.f;
#pragma unroll
            for (int i = 0; i < 16; i++) {
                float4 w = V2qa[i * 256 + tid];
                float4 v = a4[2 * i + h];
                a    = fmaf(w.x, v.x, a);    bacc = fmaf(w.y, v.y, bacc);
                a    = fmaf(w.z, v.z, a);    bacc = fmaf(w.w, v.w, bacc);
            }
            float s = a + bacc;
            s += __shfl_xor_sync(0xffffffffu, s, 1);
            if (h == 0) {
                float z = sm[OFF_C2 + rh] + s;
                float m = tanhf(z);
                msm[rh] = m; tz[rh] = 1.0f - m * m;
            }
        }
        {   // rows 128..191 (quads)
            float a = 0.f, bacc = 0.f;
#pragma unroll
            for (int i = 0; i < 8; i++) {
                float4 w = V2qb[i * 256 + tid];
                float4 v = a4[4 * i + q];
                a    = fmaf(w.x, v.x, a);    bacc = fmaf(w.y, v.y, bacc);
                a    = fmaf(w.z, v.z, a);    bacc = fmaf(w.w, v.w, bacc);
            }
            float s = a + bacc;
            s += __shfl_xor_sync(0xffffffffu, s, 1);
            s += __shfl_xor_sync(0xffffffffu, s, 2);
            if (q == 0) {
                int r = 128 + rq;
                float z = sm[OFF_C2 + r] + s;
                float m = tanhf(z);
                msm[r] = m; tz[r] = 1.0f - m * m;
            }
        }
    }
    __syncthreads();
    // ---------- JVP layer 0 (3 tangents = rows of m) ----------
    {
        const float4* m0 = (const float4*)(msm);
        const float4* m1 = (const float4*)(msm + 64);
        const float4* m2 = (const float4*)(msm + 128);
        float d0a = 0.f, d0b = 0.f, d1a = 0.f, d1b = 0.f, d2a = 0.f, d2b = 0.f;
#pragma unroll
        for (int i = 0; i < 8; i++) {
            float4 w = V0q[i * 256 + tid];
            float4 a = m0[2 * i + h];
            d0a = fmaf(w.x, a.x, fmaf(w.y, a.y, d0a));
            d0b = fmaf(w.z, a.z, fmaf(w.w, a.w, d0b));
            float4 bb = m1[2 * i + h];
            d1a = fmaf(w.x, bb.x, fmaf(w.y, bb.y, d1a));
            d1b = fmaf(w.z, bb.z, fmaf(w.w, bb.w, d1b));
            float4 cc = m2[2 * i + h];
            d2a = fmaf(w.x, cc.x, fmaf(w.y, cc.y, d2a));
            d2b = fmaf(w.z, cc.z, fmaf(w.w, cc.w, d2b));
        }
        float d0 = d0a + d0b, d1 = d1a + d1b, d2 = d2a + d2b;
        d0 += __shfl_xor_sync(0xffffffffu, d0, 1);
        d1 += __shfl_xor_sync(0xffffffffu, d1, 1);
        d2 += __shfl_xor_sync(0xffffffffu, d2, 1);
        if (h == 0) {
            float g = g0[rh];
            tn0[rh]       = g * d0;
            tn0[128 + rh] = g * d1;
            tn0[256 + rh] = g * d2;
        }
    }
    __syncthreads();
    // ---------- JVP layer 1 ----------
    {
        const float4* a0p = (const float4*)(tn0);
        const float4* a1p = (const float4*)(tn0 + 128);
        const float4* a2p = (const float4*)(tn0 + 256);
        float d0a = 0.f, d0b = 0.f, d1a = 0.f, d1b = 0.f, d2a = 0.f, d2b = 0.f;
#pragma unroll
        for (int i = 0; i < 16; i++) {
            float4 w = V1q[i * 256 + tid];
            float4 a = a0p[2 * i + h];
            d0a = fmaf(w.x, a.x, fmaf(w.y, a.y, d0a));
            d0b = fmaf(w.z, a.z, fmaf(w.w, a.w, d0b));
            float4 bb = a1p[2 * i + h];
            d1a = fmaf(w.x, bb.x, fmaf(w.y, bb.y, d1a));
            d1b = fmaf(w.z, bb.z, fmaf(w.w, bb.w, d1b));
            float4 cc = a2p[2 * i + h];
            d2a = fmaf(w.x, cc.x, fmaf(w.y, cc.y, d2a));
            d2b = fmaf(w.z, cc.z, fmaf(w.w, cc.w, d2b));
        }
        float d0 = d0a + d0b, d1 = d1a + d1b, d2 = d2a + d2b;
        d0 += __shfl_xor_sync(0xffffffffu, d0, 1);
        d1 += __shfl_xor_sync(0xffffffffu, d1, 1);
        d2 += __shfl_xor_sync(0xffffffffu, d2, 1);
        if (h == 0) {
            float g = g1[rh];
            tn1[rh]       = g * d0;
            tn1[128 + rh] = g * d1;
            tn1[256 + rh] = g * d2;
        }
    }
    __syncthreads();
    // ---------- JVP layer 2 ----------
    {
        const float4* a0p = (const float4*)(tn1);
        const float4* a1p = (const float4*)(tn1 + 128);
        const float4* a2p = (const float4*)(tn1 + 256);
        {   // rows 0..127 (pairs)
            float d0a = 0.f, d0b = 0.f, d1a = 0.f, d1b = 0.f, d2a = 0.f, d2b = 0.f;
#pragma unroll
            for (int i = 0; i < 16; i++) {
                float4 w = V2qa[i * 256 + tid];
                float4 a = a0p[2 * i + h];
                d0a = fmaf(w.x, a.x, fmaf(w.y, a.y, d0a));
                d0b = fmaf(w.z, a.z, fmaf(w.w, a.w, d0b));
                float4 bb = a1p[2 * i + h];
                d1a = fmaf(w.x, bb.x, fmaf(w.y, bb.y, d1a));
                d1b = fmaf(w.z, bb.z, fmaf(w.w, bb.w, d1b));
                float4 cc = a2p[2 * i + h];
                d2a = fmaf(w.x, cc.x, fmaf(w.y, cc.y, d2a));
                d2b = fmaf(w.z, cc.z, fmaf(w.w, cc.w, d2b));
            }
            float d0 = d0a + d0b, d1 = d1a + d1b, d2 = d2a + d2b;
            d0 += __shfl_xor_sync(0xffffffffu, d0, 1);
            d1 += __shfl_xor_sync(0xffffffffu, d1, 1);
            d2 += __shfl_xor_sync(0xffffffffu, d2, 1);
            if (h == 0) {
                float tzv = tz[rh];
                J[rh]       = tzv * d0;
                J[192 + rh] = tzv * d1;
                J[384 + rh] = tzv * d2;
            }
        }
        {   // rows 128..191 (quads)
            float d0a = 0.f, d0b = 0.f, d1a = 0.f, d1b = 0.f, d2a = 0.f, d2b = 0.f;
#pragma unroll
            for (int i = 0; i < 8; i++) {
                float4 w = V2qb[i * 256 + tid];
                float4 a = a0p[4 * i + q];
                d0a = fmaf(w.x, a.x, fmaf(w.y, a.y, d0a));
                d0b = fmaf(w.z, a.z, fmaf(w.w, a.w, d0b));
                float4 bb = a1p[4 * i + q];
                d1a = fmaf(w.x, bb.x, fmaf(w.y, bb.y, d1a));
                d1b = fmaf(w.z, bb.z, fmaf(w.w, bb.w, d1b));
                float4 cc = a2p[4 * i + q];
                d2a = fmaf(w.x, cc.x, fmaf(w.y, cc.y, d2a));
                d2b = fmaf(w.z, cc.z, fmaf(w.w, cc.w, d2b));
            }
            float d0 = d0a + d0b, d1 = d1a + d1b, d2 = d2a + d2b;
            d0 += __shfl_xor_sync(0xffffffffu, d0, 1);
            d0 += __shfl_xor_sync(0xffffffffu, d0, 2);
            d1 += __shfl_xor_sync(0xffffffffu, d1, 1);
            d1 += __shfl_xor_sync(0xffffffffu, d1, 2);
            d2 += __shfl_xor_sync(0xffffffffu, d2, 1);
            d2 += __shfl_xor_sync(0xffffffffu, d2, 2);
            if (q == 0) {
                int r = 128 + rq;
                float tzv = tz[r];
                J[r]       = tzv * d0;
                J[192 + r] = tzv * d1;
                J[384 + r] = tzv * d2;
            }
        }
    }
    __syncthreads();
    // ---------- combine: k[h] = m.T s[0:3] + br.T s[3:6] ----------
    float k = 0.f;
    if (tid < 64) {
        k =  msm[tid]        * svec[0]
           + msm[64 + tid]   * svec[1]
           + msm[128 + tid]  * svec[2]
           + (J[64 + tid]  - J[192 + tid]) * svec[3]
           + (J[128 + tid] - J[384 + tid]) * svec[4]
           + (J[320 + tid] - J[448 + tid]) * svec[5];
    }
    return k;
}

// Output projection: out_row[o] = tanh(dot(y, R[o,:]) + rb[o])
// 256 threads: 8 threads per output, 8-dim partials, shuffle-reduce.
__device__ __forceinline__ void write_out_row(const float* sm, int t, float* __restrict__ dst)
{
    int o = t >> 3, part = t & 7;
    const float* r = sm + OFF_R + o * 64 + part * 8;
    const float* y = sm + OFF_Y + part * 8;
    float s = 0.f;
#pragma unroll
    for (int j = 0; j < 8; j++) s = fmaf(r[j], y[j], s);
    s += __shfl_xor_sync(0xffffffffu, s, 1);
    s += __shfl_xor_sync(0xffffffffu, s, 2);
    s += __shfl_xor_sync(0xffffffffu, s, 4);
    if (part == 0) dst[o] = tanhf(s + sm[OFF_RB + o]);
}

__global__ void __launch_bounds__(NTHREADS, 1)
ncde_kernel(const float* __restrict__ ts, const float* __restrict__ x,
            const float* __restrict__ W0, const float* __restrict__ b0,
            const float* __restrict__ W1, const float* __restrict__ b1,
            const float* __restrict__ W2, const float* __restrict__ b2,
            const float* __restrict__ V0, const float* __restrict__ c0,
            const float* __restrict__ V1, const float* __restrict__ c1,
            const float* __restrict__ V2, const float* __restrict__ c2,
            const float* __restrict__ R,  const float* __restrict__ rb,
            float* __restrict__ out)
{
    extern __shared__ float sm[];
    const int t = threadIdx.x;
    const int b = blockIdx.x;

    // ---- stage weights into smem in split-K packed layouts ----
    for (int idx = t; idx < 8 * 256; idx += NTHREADS) {       // V0q
        int i = idx >> 8, tt = idx & 255;
        int r = tt >> 1, h = tt & 1;
        ((float4*)(sm + OFF_V0Q))[idx] = *(const float4*)(V0 + r * 64 + (2 * i + h) * 4);
    }
    for (int idx = t; idx < 16 * 256; idx += NTHREADS) {      // V1q
        int i = idx >> 8, tt = idx & 255;
        int r = tt >> 1, h = tt & 1;
        ((float4*)(sm + OFF_V1Q))[idx] = *(const float4*)(V1 + r * 128 + (2 * i + h) * 4);
    }
    for (int idx = t; idx < 16 * 256; idx += NTHREADS) {      // V2qa (rows 0..127)
        int i = idx >> 8, tt = idx & 255;
        int r = tt >> 1, h = tt & 1;
        ((float4*)(sm + OFF_V2QA))[idx] = *(const float4*)(V2 + r * 128 + (2 * i + h) * 4);
    }
    for (int idx = t; idx < 8 * 256; idx += NTHREADS) {       // V2qb (rows 128..191)
        int i = idx >> 8, tt = idx & 255;
        int rp = tt >> 2, q = tt & 3;
        ((float4*)(sm + OFF_V2QB))[idx] = *(const float4*)(V2 + (128 + rp) * 128 + (4 * i + q) * 4);
    }
    for (int i = t; i < 2048; i += NTHREADS) sm[OFF_R + i] = R[i];
    if (t < 32) sm[OFF_RB + t] = rb[t];
    if (t < 128) { sm[OFF_C0 + t] = c0[t]; sm[OFF_C1 + t] = c1[t]; }
    for (int i = t; i < 192; i += NTHREADS) sm[OFF_C2 + i] = c2[i];

    // ---- per-batch: dt array ----
    {
        const float* tsb = ts + b * TLEN;
        for (int i = t; i < NSTEP; i += NTHREADS) sm[OFF_DTS + i] = tsb[i + 1] - tsb[i];
    }

    // ---- per-batch: window log-signature slopes (16 windows x 6 channels) ----
    if (t < NWIN) {
        const float* xp = x + (b * TLEN + t * 8) * 3;
        float p[9][3];
#pragma unroll
        for (int k = 0; k < 9; k++) {
            p[k][0] = xp[k * 3 + 0];
            p[k][1] = xp[k * 3 + 1];
            p[k][2] = xp[k * 3 + 2];
        }
        float a01 = 0.f, a10 = 0.f, a02 = 0.f, a20 = 0.f, a12 = 0.f, a21 = 0.f;
#pragma unroll
        for (int k = 0; k < 8; k++) {
            float r0 = p[k][0] - p[0][0], r1 = p[k][1] - p[0][1], r2 = p[k][2] - p[0][2];
            float d0 = p[k + 1][0] - p[k][0], d1 = p[k + 1][1] - p[k][1], d2 = p[k + 1][2] - p[k][2];
            a01 = fmaf(r0, d1, a01); a10 = fmaf(r1, d0, a10);
            a02 = fmaf(r0, d2, a02); a20 = fmaf(r2, d0, a20);
            a12 = fmaf(r1, d2, a12); a21 = fmaf(r2, d1, a21);
        }
        const float* tsb = ts + b * TLEN;
        float td = tsb[(t + 1) * 8] - tsb[t * 8];
        float* sl = sm + OFF_SLP + t * 8;
        sl[0] = (p[8][0] - p[0][0]) / td;
        sl[1] = (p[8][1] - p[0][1]) / td;
        sl[2] = (p[8][2] - p[0][2]) / td;
        sl[3] = (0.5f * (a01 - a10)) / td;
        sl[4] = (0.5f * (a02 - a20)) / td;
        sl[5] = (0.5f * (a12 - a21)) / td;
    }
    __syncthreads();

    // ---- init MLP: h0 = W2 @ sp(W1 @ sp(W0 @ x0 + b0) + b1) + b2 ----
    if (t < 128) {
        const float* xp = x + b * TLEN * 3;
        float x0 = xp[0], x1 = xp[1], x2 = xp[2];
        float u = b0[t] + W0[t * 3] * x0 + W0[t * 3 + 1] * x1 + W0[t * 3 + 2] * x2;
        sm[OFF_S0 + t] = softplusf(u);
    }
    __syncthreads();
    if (t < 128) {
        float acc = b1[t];
        const float* w = W1 + t * 128;
#pragma unroll 4
        for (int j = 0; j < 128; j++) acc = fmaf(w[j], sm[OFF_S0 + j], acc);
        sm[OFF_S1 + t] = softplusf(acc);
    }
    __syncthreads();
    if (t < 64) {
        float acc = b2[t];
        const float* w = W2 + t * 128;
#pragma unroll 4
        for (int j = 0; j < 128; j++) acc = fmaf(w[j], sm[OFF_S1 + j], acc);
        sm[OFF_Y + t] = acc;
    }
    __syncthreads();

    // ---- output row 0 (from h0) ----
    write_out_row(sm, t, out + (b * TLEN + 0) * OUTN);

    // ---- RK2 (Heun) scan over 128 steps ----
    for (int i = 0; i < NSTEP; i++) {
        float dt = sm[OFF_DTS + i];
        const float* svec = sm + OFF_SLP + ((i >> 3) << 3);

        float k1 = eval_F(sm, t, sm + OFF_Y, svec);
        if (t < 64) sm[OFF_Y2 + t] = sm[OFF_Y + t] + dt * k1;
        __syncthreads();

        float k2 = eval_F(sm, t, sm + OFF_Y2, svec);
        if (t < 64) sm[OFF_Y + t] += 0.5f * dt * (k1 + k2);
        __syncthreads();

        write_out_row(sm, t, out + (b * TLEN + i + 1) * OUTN);
    }
}

extern "C" void kernel_launch(void* const* d_in, const int* in_sizes, int n_in,
                              void* d_out, int out_size)
{
    const float* ts = (const float*)d_in[0];
    const float* x  = (const float*)d_in[1];
    const float* W0 = (const float*)d_in[2];
    const float* b0 = (const float*)d_in[3];
    const float* W1 = (const float*)d_in[4];
    const float* b1 = (const float*)d_in[5];
    const float* W2 = (const float*)d_in[6];
    const float* b2 = (const float*)d_in[7];
    const float* V0 = (const float*)d_in[8];
    const float* c0 = (const float*)d_in[9];
    const float* V1 = (const float*)d_in[10];
    const float* c1 = (const float*)d_in[11];
    const float* V2 = (const float*)d_in[12];
    const float* c2 = (const float*)d_in[13];
    const float* R  = (const float*)d_in[14];
    const float* rb = (const float*)d_in[15];
    float* out = (float*)d_out;

    cudaFuncSetAttribute(ncde_kernel, cudaFuncAttributeMaxDynamicSharedMemorySize, SMEM_BYTES);
    ncde_kernel<<<BATCH, NTHREADS, SMEM_BYTES>>>(ts, x, W0, b0, W1, b1, W2, b2,
                                                 V0, c0, V1, c1, V2, c2, R, rb, out);
}

// round 9
// speedup vs baseline: 2.4655x; 1.3750x over previous
#include <cuda_runtime.h>
#include <math.h>

// Problem constants
#define NTHREADS 256
#define BATCH    128
#define TLEN     129
#define NSTEP    128   // TLEN-1
#define NWIN     16    // (TLEN-1)/8
#define OUTN     32

// ---- shared memory layout (float offsets) ----
// Only V2 rows 128..191 stay in SMEM (quad split-K layout):
//   V2qb[i][tid] (8x256 float4): tid=4r'+q -> V2[128+r'][(4i+q)*4 ..]
// V0 / V1 / V2 rows 0..127 live in per-thread registers (packed f32x2).
#define OFF_V2QB 0        // 8192
#define OFF_R    8192     // 2048  (R row-major 32x64)
#define OFF_RB   10240    // 32
#define OFF_C0   10272    // 128
#define OFF_C1   10400    // 128
#define OFF_C2   10528    // 192
#define OFF_Y    10720    // 64
#define OFF_Y2   10784    // 64
#define OFF_S0   10848    // 128
#define OFF_G0   10976    // 128
#define OFF_S1   11104    // 128
#define OFF_G1   11232    // 128
#define OFF_M    11360    // 192
#define OFF_TZ   11552    // 192
#define OFF_TN0  11744    // 3*128
#define OFF_TN1  12128    // 3*128
#define OFF_J    12512    // 3*192
#define OFF_SLP  13088    // 16*8 (6 used per window)
#define OFF_DTS  13216    // 128
#define SMEM_FLOATS 13344
#define SMEM_BYTES  (SMEM_FLOATS * 4)

typedef unsigned long long u64;

__device__ __forceinline__ float softplusf(float x) {
    // jax.nn.softplus == max(x,0) + log1p(exp(-|x|))
    return fmaxf(x, 0.0f) + log1pf(expf(-fabsf(x)));
}
__device__ __forceinline__ float sigmoidf_(float x) {
    return 1.0f / (1.0f + expf(-x));
}

// packed f32x2 fma: lanewise d = a*b + c
__device__ __forceinline__ u64 ffma2(u64 a, u64 b, u64 c) {
    u64 d;
    asm("fma.rn.f32x2 %0, %1, %2, %3;" : "=l"(d) : "l"(a), "l"(b), "l"(c));
    return d;
}
// horizontal add of the two f32 lanes
__device__ __forceinline__ float hadd2(u64 v) {
    unsigned lo, hi;
    asm("mov.b64 {%0, %1}, %2;" : "=r"(lo), "=r"(hi) : "l"(v));
    return __uint_as_float(lo) + __uint_as_float(hi);
}
// LDS.128 into two packed f32x2 (64-bit register pairs), no MOV packing
__device__ __forceinline__ void lds_v2u64(const float* p, u64& a, u64& b) {
    unsigned addr = (unsigned)__cvta_generic_to_shared(p);
    asm volatile("ld.shared.v2.u64 {%0, %1}, [%2];" : "=l"(a), "=l"(b) : "r"(addr));
}

// F(y) . s. 256 threads, split-K pair/quad scheme, register-resident weights.
// Returns k[tid] in a register (valid for tid<64). Caller must ensure yin is
// visible on entry and barrier before reusing shared scratch.
__device__ __forceinline__ float eval_F(float* sm, int tid,
                                        const float* __restrict__ yin,
                                        const float* __restrict__ svec,
                                        const u64* __restrict__ w0p,   // 16 (V0 row rh)
                                        const u64* __restrict__ w1p,   // 32 (V1 row rh)
                                        const u64* __restrict__ w2p)   // 32 (V2 row rh)
{
    const int rh = tid >> 1, h = tid & 1;    // pair mapping (128 rows x 2)
    const int rq = tid >> 2, q = tid & 3;    // quad mapping (64 rows x 4)
    float* s0  = sm + OFF_S0;  float* g0 = sm + OFF_G0;
    float* s1  = sm + OFF_S1;  float* g1 = sm + OFF_G1;
    float* msm = sm + OFF_M;   float* tz = sm + OFF_TZ;
    float* tn0 = sm + OFF_TN0; float* tn1 = sm + OFF_TN1;
    float* J   = sm + OFF_J;
    const float* V2qb = sm + OFF_V2QB;

    // ---------- forward layer 0: u0 = V0 @ y + c0 ----------
    {
        u64 acc = 0ull;
#pragma unroll
        for (int i = 0; i < 8; i++) {
            u64 a0, a1;
            lds_v2u64(yin + (2 * i + h) * 4, a0, a1);
            acc = ffma2(w0p[2 * i], a0, acc);
            acc = ffma2(w0p[2 * i + 1], a1, acc);
        }
        float s = hadd2(acc);
        s += __shfl_xor_sync(0xffffffffu, s, 1);
        if (h == 0) {
            float u = sm[OFF_C0 + rh] + s;
            s0[rh] = softplusf(u);
            g0[rh] = sigmoidf_(u);
        }
    }
    __syncthreads();
    // ---------- forward layer 1 ----------
    {
        u64 acc = 0ull;
#pragma unroll
        for (int i = 0; i < 16; i++) {
            u64 a0, a1;
            lds_v2u64(s0 + (2 * i + h) * 4, a0, a1);
            acc = ffma2(w1p[2 * i], a0, acc);
            acc = ffma2(w1p[2 * i + 1], a1, acc);
        }
        float s = hadd2(acc);
        s += __shfl_xor_sync(0xffffffffu, s, 1);
        if (h == 0) {
            float u = sm[OFF_C1 + rh] + s;
            s1[rh] = softplusf(u);
            g1[rh] = sigmoidf_(u);
        }
    }
    __syncthreads();
    // ---------- forward layer 2 (192 rows) ----------
    {
        {   // rows 0..127 (pairs, register weights)
            u64 acc = 0ull;
#pragma unroll
            for (int i = 0; i < 16; i++) {
                u64 a0, a1;
                lds_v2u64(s1 + (2 * i + h) * 4, a0, a1);
                acc = ffma2(w2p[2 * i], a0, acc);
                acc = ffma2(w2p[2 * i + 1], a1, acc);
            }
            float s = hadd2(acc);
            s += __shfl_xor_sync(0xffffffffu, s, 1);
            if (h == 0) {
                float z = sm[OFF_C2 + rh] + s;
                float m = tanhf(z);
                msm[rh] = m; tz[rh] = 1.0f - m * m;
            }
        }
        {   // rows 128..191 (quads, SMEM weights)
            u64 acc = 0ull;
#pragma unroll
            for (int i = 0; i < 8; i++) {
                u64 w0, w1, a0, a1;
                lds_v2u64(V2qb + (i * 256 + tid) * 4, w0, w1);
                lds_v2u64(s1 + (4 * i + q) * 4, a0, a1);
                acc = ffma2(w0, a0, acc);
                acc = ffma2(w1, a1, acc);
            }
            float s = hadd2(acc);
            s += __shfl_xor_sync(0xffffffffu, s, 1);
            s += __shfl_xor_sync(0xffffffffu, s, 2);
            if (q == 0) {
                int r = 128 + rq;
                float z = sm[OFF_C2 + r] + s;
                float m = tanhf(z);
                msm[r] = m; tz[r] = 1.0f - m * m;
            }
        }
    }
    __syncthreads();
    // ---------- JVP layer 0 (3 tangents = rows of m) ----------
    {
        u64 d0 = 0ull, d1 = 0ull, d2 = 0ull;
#pragma unroll
        for (int i = 0; i < 8; i++) {
            u64 a0, a1, b0, b1, c0v, c1v;
            lds_v2u64(msm + (2 * i + h) * 4, a0, a1);
            lds_v2u64(msm + 64 + (2 * i + h) * 4, b0, b1);
            lds_v2u64(msm + 128 + (2 * i + h) * 4, c0v, c1v);
            u64 wa = w0p[2 * i], wb = w0p[2 * i + 1];
            d0 = ffma2(wa, a0, d0);  d0 = ffma2(wb, a1, d0);
            d1 = ffma2(wa, b0, d1);  d1 = ffma2(wb, b1, d1);
            d2 = ffma2(wa, c0v, d2); d2 = ffma2(wb, c1v, d2);
        }
        float e0 = hadd2(d0), e1 = hadd2(d1), e2 = hadd2(d2);
        e0 += __shfl_xor_sync(0xffffffffu, e0, 1);
        e1 += __shfl_xor_sync(0xffffffffu, e1, 1);
        e2 += __shfl_xor_sync(0xffffffffu, e2, 1);
        if (h == 0) {
            float g = g0[rh];
            tn0[rh]       = g * e0;
            tn0[128 + rh] = g * e1;
            tn0[256 + rh] = g * e2;
        }
    }
    __syncthreads();
    // ---------- JVP layer 1 ----------
    {
        u64 d0 = 0ull, d1 = 0ull, d2 = 0ull;
#pragma unroll
        for (int i = 0; i < 16; i++) {
            u64 a0, a1, b0, b1, c0v, c1v;
            lds_v2u64(tn0 + (2 * i + h) * 4, a0, a1);
            lds_v2u64(tn0 + 128 + (2 * i + h) * 4, b0, b1);
            lds_v2u64(tn0 + 256 + (2 * i + h) * 4, c0v, c1v);
            u64 wa = w1p[2 * i], wb = w1p[2 * i + 1];
            d0 = ffma2(wa, a0, d0);  d0 = ffma2(wb, a1, d0);
            d1 = ffma2(wa, b0, d1);  d1 = ffma2(wb, b1, d1);
            d2 = ffma2(wa, c0v, d2); d2 = ffma2(wb, c1v, d2);
        }
        float e0 = hadd2(d0), e1 = hadd2(d1), e2 = hadd2(d2);
        e0 += __shfl_xor_sync(0xffffffffu, e0, 1);
        e1 += __shfl_xor_sync(0xffffffffu, e1, 1);
        e2 += __shfl_xor_sync(0xffffffffu, e2, 1);
        if (h == 0) {
            float g = g1[rh];
            tn1[rh]       = g * e0;
            tn1[128 + rh] = g * e1;
            tn1[256 + rh] = g * e2;
        }
    }
    __syncthreads();
    // ---------- JVP layer 2 ----------
    {
        {   // rows 0..127 (pairs, register weights)
            u64 d0 = 0ull, d1 = 0ull, d2 = 0ull;
#pragma unroll
            for (int i = 0; i < 16; i++) {
                u64 a0, a1, b0, b1, c0v, c1v;
                lds_v2u64(tn1 + (2 * i + h) * 4, a0, a1);
                lds_v2u64(tn1 + 128 + (2 * i + h) * 4, b0, b1);
                lds_v2u64(tn1 + 256 + (2 * i + h) * 4, c0v, c1v);
                u64 wa = w2p[2 * i], wb = w2p[2 * i + 1];
                d0 = ffma2(wa, a0, d0);  d0 = ffma2(wb, a1, d0);
                d1 = ffma2(wa, b0, d1);  d1 = ffma2(wb, b1, d1);
                d2 = ffma2(wa, c0v, d2); d2 = ffma2(wb, c1v, d2);
            }
            float e0 = hadd2(d0), e1 = hadd2(d1), e2 = hadd2(d2);
            e0 += __shfl_xor_sync(0xffffffffu, e0, 1);
            e1 += __shfl_xor_sync(0xffffffffu, e1, 1);
            e2 += __shfl_xor_sync(0xffffffffu, e2, 1);
            if (h == 0) {
                float tzv = tz[rh];
                J[rh]       = tzv * e0;
                J[192 + rh] = tzv * e1;
                J[384 + rh] = tzv * e2;
            }
        }
        {   // rows 128..191 (quads, SMEM weights)
            u64 d0 = 0ull, d1 = 0ull, d2 = 0ull;
#pragma unroll
            for (int i = 0; i < 8; i++) {
                u64 w0, w1, a0, a1, b0, b1, c0v, c1v;
                lds_v2u64(V2qb + (i * 256 + tid) * 4, w0, w1);
                lds_v2u64(tn1 + (4 * i + q) * 4, a0, a1);
                lds_v2u64(tn1 + 128 + (4 * i + q) * 4, b0, b1);
                lds_v2u64(tn1 + 256 + (4 * i + q) * 4, c0v, c1v);
                d0 = ffma2(w0, a0, d0);  d0 = ffma2(w1, a1, d0);
                d1 = ffma2(w0, b0, d1);  d1 = ffma2(w1, b1, d1);
                d2 = ffma2(w0, c0v, d2); d2 = ffma2(w1, c1v, d2);
            }
            float e0 = hadd2(d0), e1 = hadd2(d1), e2 = hadd2(d2);
            e0 += __shfl_xor_sync(0xffffffffu, e0, 1);
            e0 += __shfl_xor_sync(0xffffffffu, e0, 2);
            e1 += __shfl_xor_sync(0xffffffffu, e1, 1);
            e1 += __shfl_xor_sync(0xffffffffu, e1, 2);
            e2 += __shfl_xor_sync(0xffffffffu, e2, 1);
            e2 += __shfl_xor_sync(0xffffffffu, e2, 2);
            if (q == 0) {
                int r = 128 + rq;
                float tzv = tz[r];
                J[r]       = tzv * e0;
                J[192 + r] = tzv * e1;
                J[384 + r] = tzv * e2;
            }
        }
    }
    __syncthreads();
    // ---------- combine: k[h] = m.T s[0:3] + br.T s[3:6] ----------
    float k = 0.f;
    if (tid < 64) {
        k =  msm[tid]        * svec[0]
           + msm[64 + tid]   * svec[1]
           + msm[128 + tid]  * svec[2]
           + (J[64 + tid]  - J[192 + tid]) * svec[3]
           + (J[128 + tid] - J[384 + tid]) * svec[4]
           + (J[320 + tid] - J[448 + tid]) * svec[5];
    }
    return k;
}

// Output projection: out_row[o] = tanh(dot(y, R[o,:]) + rb[o])
__device__ __forceinline__ void write_out_row(const float* sm, int t, float* __restrict__ dst)
{
    int o = t >> 3, part = t & 7;
    const float* r = sm + OFF_R + o * 64 + part * 8;
    const float* y = sm + OFF_Y + part * 8;
    float s = 0.f;
#pragma unroll
    for (int j = 0; j < 8; j++) s = fmaf(r[j], y[j], s);
    s += __shfl_xor_sync(0xffffffffu, s, 1);
    s += __shfl_xor_sync(0xffffffffu, s, 2);
    s += __shfl_xor_sync(0xffffffffu, s, 4);
    if (part == 0) dst[o] = tanhf(s + sm[OFF_RB + o]);
}

__global__ void __launch_bounds__(NTHREADS, 1)
ncde_kernel(const float* __restrict__ ts, const float* __restrict__ x,
            const float* __restrict__ W0, const float* __restrict__ b0,
            const float* __restrict__ W1, const float* __restrict__ b1,
            const float* __restrict__ W2, const float* __restrict__ b2,
            const float* __restrict__ V0, const float* __restrict__ c0,
            const float* __restrict__ V1, const float* __restrict__ c1,
            const float* __restrict__ V2, const float* __restrict__ c2,
            const float* __restrict__ R,  const float* __restrict__ rb,
            float* __restrict__ out)
{
    extern __shared__ float sm[];
    const int t = threadIdx.x;
    const int b = blockIdx.x;
    const int rh = t >> 1, h = t & 1;

    // ---- pin per-thread weight slices in registers (packed f32x2) ----
    u64 w0p[16], w1p[32], w2p[32];
#pragma unroll
    for (int i = 0; i < 8; i++) {
        ulonglong2 v = *(const ulonglong2*)(V0 + rh * 64 + (2 * i + h) * 4);
        w0p[2 * i] = v.x; w0p[2 * i + 1] = v.y;
    }
#pragma unroll
    for (int i = 0; i < 16; i++) {
        ulonglong2 v = *(const ulonglong2*)(V1 + rh * 128 + (2 * i + h) * 4);
        w1p[2 * i] = v.x; w1p[2 * i + 1] = v.y;
    }
#pragma unroll
    for (int i = 0; i < 16; i++) {
        ulonglong2 v = *(const ulonglong2*)(V2 + rh * 128 + (2 * i + h) * 4);
        w2p[2 * i] = v.x; w2p[2 * i + 1] = v.y;
    }

    // ---- stage V2 rows 128..191 into SMEM (quad split-K layout) ----
    for (int idx = t; idx < 8 * 256; idx += NTHREADS) {
        int i = idx >> 8, tt = idx & 255;
        int rp = tt >> 2, q = tt & 3;
        ((float4*)(sm + OFF_V2QB))[idx] = *(const float4*)(V2 + (128 + rp) * 128 + (4 * i + q) * 4);
    }
    for (int i = t; i < 2048; i += NTHREADS) sm[OFF_R + i] = R[i];
    if (t < 32) sm[OFF_RB + t] = rb[t];
    if (t < 128) { sm[OFF_C0 + t] = c0[t]; sm[OFF_C1 + t] = c1[t]; }
    for (int i = t; i < 192; i += NTHREADS) sm[OFF_C2 + i] = c2[i];

    // ---- per-batch: dt array ----
    {
        const float* tsb = ts + b * TLEN;
        for (int i = t; i < NSTEP; i += NTHREADS) sm[OFF_DTS + i] = tsb[i + 1] - tsb[i];
    }

    // ---- per-batch: window log-signature slopes (16 windows x 6 channels) ----
    if (t < NWIN) {
        const float* xp = x + (b * TLEN + t * 8) * 3;
        float p[9][3];
#pragma unroll
        for (int k = 0; k < 9; k++) {
            p[k][0] = xp[k * 3 + 0];
            p[k][1] = xp[k * 3 + 1];
            p[k][2] = xp[k * 3 + 2];
        }
        float a01 = 0.f, a10 = 0.f, a02 = 0.f, a20 = 0.f, a12 = 0.f, a21 = 0.f;
#pragma unroll
        for (int k = 0; k < 8; k++) {
            float r0 = p[k][0] - p[0][0], r1 = p[k][1] - p[0][1], r2 = p[k][2] - p[0][2];
            float d0 = p[k + 1][0] - p[k][0], d1 = p[k + 1][1] - p[k][1], d2 = p[k + 1][2] - p[k][2];
            a01 = fmaf(r0, d1, a01); a10 = fmaf(r1, d0, a10);
            a02 = fmaf(r0, d2, a02); a20 = fmaf(r2, d0, a20);
            a12 = fmaf(r1, d2, a12); a21 = fmaf(r2, d1, a21);
        }
        const float* tsb = ts + b * TLEN;
        float td = tsb[(t + 1) * 8] - tsb[t * 8];
        float* sl = sm + OFF_SLP + t * 8;
        sl[0] = (p[8][0] - p[0][0]) / td;
        sl[1] = (p[8][1] - p[0][1]) / td;
        sl[2] = (p[8][2] - p[0][2]) / td;
        sl[3] = (0.5f * (a01 - a10)) / td;
        sl[4] = (0.5f * (a02 - a20)) / td;
        sl[5] = (0.5f * (a12 - a21)) / td;
    }
    __syncthreads();

    // ---- init MLP: h0 = W2 @ sp(W1 @ sp(W0 @ x0 + b0) + b1) + b2 ----
    if (t < 128) {
        const float* xp = x + b * TLEN * 3;
        float x0 = xp[0], x1 = xp[1], x2 = xp[2];
        float u = b0[t] + W0[t * 3] * x0 + W0[t * 3 + 1] * x1 + W0[t * 3 + 2] * x2;
        sm[OFF_S0 + t] = softplusf(u);
    }
    __syncthreads();
    if (t < 128) {
        float acc = b1[t];
        const float* w = W1 + t * 128;
#pragma unroll 4
        for (int j = 0; j < 128; j++) acc = fmaf(w[j], sm[OFF_S0 + j], acc);
        sm[OFF_S1 + t] = softplusf(acc);
    }
    __syncthreads();
    if (t < 64) {
        float acc = b2[t];
        const float* w = W2 + t * 128;
#pragma unroll 4
        for (int j = 0; j < 128; j++) acc = fmaf(w[j], sm[OFF_S1 + j], acc);
        sm[OFF_Y + t] = acc;
    }
    __syncthreads();

    // ---- output row 0 (from h0) ----
    write_out_row(sm, t, out + (b * TLEN + 0) * OUTN);

    // ---- RK2 (Heun) scan over 128 steps ----
    for (int i = 0; i < NSTEP; i++) {
        float dt = sm[OFF_DTS + i];
        const float* svec = sm + OFF_SLP + ((i >> 3) << 3);

        float k1 = eval_F(sm, t, sm + OFF_Y, svec, w0p, w1p, w2p);
        if (t < 64) sm[OFF_Y2 + t] = sm[OFF_Y + t] + dt * k1;
        __syncthreads();

        float k2 = eval_F(sm, t, sm + OFF_Y2, svec, w0p, w1p, w2p);
        if (t < 64) sm[OFF_Y + t] += 0.5f * dt * (k1 + k2);
        __syncthreads();

        write_out_row(sm, t, out + (b * TLEN + i + 1) * OUTN);
    }
}

extern "C" void kernel_launch(void* const* d_in, const int* in_sizes, int n_in,
                              void* d_out, int out_size)
{
    const float* ts = (const float*)d_in[0];
    const float* x  = (const float*)d_in[1];
    const float* W0 = (const float*)d_in[2];
    const float* b0 = (const float*)d_in[3];
    const float* W1 = (const float*)d_in[4];
    const float* b1 = (const float*)d_in[5];
    const float* W2 = (const float*)d_in[6];
    const float* b2 = (const float*)d_in[7];
    const float* V0 = (const float*)d_in[8];
    const float* c0 = (const float*)d_in[9];
    const float* V1 = (const float*)d_in[10];
    const float* c1 = (const float*)d_in[11];
    const float* V2 = (const float*)d_in[12];
    const float* c2 = (const float*)d_in[13];
    const float* R  = (const float*)d_in[14];
    const float* rb = (const float*)d_in[15];
    float* out = (float*)d_out;

    cudaFuncSetAttribute(ncde_kernel, cudaFuncAttributeMaxDynamicSharedMemorySize, SMEM_BYTES);
    ncde_kernel<<<BATCH, NTHREADS, SMEM_BYTES>>>(ts, x, W0, b0, W1, b1, W2, b2,
                                                 V0, c0, V1, c1, V2, c2, R, rb, out);
}